// round 13
// baseline (speedup 1.0000x reference)
#include <cuda_runtime.h>
#include <math.h>

#define G 128
#define NPG0 256
#define NNODE (G*NPG0)      // 32768
#define NF 128
#define EPG 4096
#define NE (G*EPG)          // 524288
#define KCONV (NF*9)        // 1152
#define KFC (256*9)         // 2304
#define CH 8                // inputs per K-chunk in kan_gemm
#define KR (CH*9)           // 72 K-rows per chunk
#define TN 128              // nodes per kan_gemm CTA tile
#define WSP 132             // padded Ws stride in input_linear (bank-conflict fix)

// ---------------- scratch (device globals; no allocation) ----------------
// INVARIANT: these symbols are referenced from DEVICE code only. Host code
// passing &d_xxx passes the host shadow address (UB -> 128MiB driver alloc
// that trips _HX_ENFORCE). Host selects buffers via the `lev` integer.
__device__ float d_xbuf[NNODE*NF];          // 16 MiB
__device__ float d_agg [NNODE*NF];          // 16 MiB (gemm writes back in place)
__device__ int   d_srcA[NE];                // 2 MiB
__device__ int   d_dstA[NE];                // 2 MiB
__device__ int   d_srcB[NE];                // 2 MiB
__device__ int   d_dstB[NE];                // 2 MiB
__device__ int   d_ecntA[G];
__device__ int   d_ecntB[G];
__device__ float d_read[2*3*G*256];         // 0.75 MiB
__device__ float d_wconvT[6*KCONV*NF];      // 3.4 MiB
__device__ float d_wfcgT[2*KFC*256];        // 4.5 MiB
__device__ float d_wfinT[2*KFC];
__device__ float d_xg[2*G*256];

// ---------------- packed f32x2 helpers (sm_100+ PTX) ----------------
__device__ __forceinline__ unsigned long long pk2(float lo, float hi){
    unsigned long long r;
    asm("mov.b64 %0, {%1, %2};" : "=l"(r) : "f"(lo), "f"(hi));
    return r;
}
__device__ __forceinline__ void upk2(unsigned long long v, float& lo, float& hi){
    asm("mov.b64 {%0, %1}, %2;" : "=f"(lo), "=f"(hi) : "l"(v));
}
__device__ __forceinline__ void ffma2(unsigned long long& acc, unsigned long long a,
                                      unsigned long long b){
    asm("fma.rn.f32x2 %0, %1, %2, %0;" : "+l"(acc) : "l"(a), "l"(b));
}

// ---------------- B-spline basis (cubic, GRID=5, 8 outputs) ----------------
__device__ __forceinline__ float knot(int j){ return (float)(j-3)*0.4f - 1.0f; }

__device__ __forceinline__ void bsplines8(float x, float* out){
    float b[11];
#pragma unroll
    for (int j = 0; j < 11; j++){
        float g0 = knot(j), g1 = knot(j+1);
        b[j] = (x >= g0 && x < g1) ? 1.0f : 0.0f;
    }
#pragma unroll
    for (int k = 1; k <= 3; k++){
#pragma unroll
        for (int j = 0; j <= 10-k; j++){
            float gj  = knot(j),     gjk  = knot(j+k);
            float gj1 = knot(j+1),   gjk1 = knot(j+k+1);
            b[j] = (x - gj)*(1.0f/(gjk - gj))*b[j]
                 + (gjk1 - x)*(1.0f/(gjk1 - gj1))*b[j+1];
        }
    }
#pragma unroll
    for (int j = 0; j < 8; j++) out[j] = b[j];
}

// ---------------- weight prep (transpose to [K][out]) ----------------
__global__ void prep_conv(const float* __restrict__ bw, const float* __restrict__ sw){
    int idx = blockIdx.x*blockDim.x + threadIdx.x;
    if (idx >= 6*KCONV*NF) return;
    int o = idx % NF;
    int kk = (idx / NF) % KCONV;
    int l = idx / (NF*KCONV);
    int i = kk / 9, s = kk % 9;
    float v = (s==0) ? bw[(l*NF + o)*NF + i]
                     : sw[((l*NF + o)*NF + i)*8 + (s-1)];
    d_wconvT[idx] = v;
}
__global__ void prep_fcg(const float* __restrict__ bw, const float* __restrict__ sw){
    int idx = blockIdx.x*blockDim.x + threadIdx.x;
    if (idx >= 2*KFC*256) return;
    int o = idx % 256;
    int kk = (idx / 256) % KFC;
    int l = idx / (256*KFC);
    int i = kk / 9, s = kk % 9;
    float v = (s==0) ? bw[(l*256 + o)*256 + i]
                     : sw[((l*256 + o)*256 + i)*8 + (s-1)];
    d_wfcgT[idx] = v;
}
__global__ void prep_fin(const float* __restrict__ bw, const float* __restrict__ sw){
    int idx = blockIdx.x*blockDim.x + threadIdx.x;
    if (idx >= 2*KFC) return;
    int kk = idx % KFC;
    int l = idx / KFC;
    int i = kk / 9, s = kk % 9;
    float v = (s==0) ? bw[l*256 + i] : sw[(l*256 + i)*8 + (s-1)];
    d_wfinT[idx] = v;
}

// ---------------- input linear: x = feat @ w.T + b -> d_xbuf ----------------
__global__ void __launch_bounds__(256) input_linear(
        const float* __restrict__ feat, const float* __restrict__ w,
        const float* __restrict__ bias, int IN){
    extern __shared__ float sm[];
    float* As = sm;              // [64][96]
    float* Ws = sm + 64*96;      // [96][WSP]  (row = input i; padded stride kills conflicts)
    int tid = threadIdx.x;
    int nbase = blockIdx.x * 64;
    for (int idx = tid; idx < 64*IN; idx += 256){
        int n = idx / IN, i = idx % IN;
        As[n*96 + i] = feat[(size_t)(nbase+n)*IN + i];
    }
    for (int idx = tid; idx < NF*IN; idx += 256){
        int o = idx / IN, i = idx % IN;
        Ws[i*WSP + o] = w[idx];
    }
    __syncthreads();
    int ng = (tid >> 5) * 8;
    int og = (tid & 31) * 4;
    unsigned long long acc[4][4];
#pragma unroll
    for (int p = 0; p < 4; p++)
#pragma unroll
        for (int c = 0; c < 4; c++) acc[p][c] = 0ull;
    for (int k = 0; k < IN; k++){
        float4 w4 = *(float4*)&Ws[k*WSP + og];
        unsigned long long w0 = pk2(w4.x, w4.x), w1 = pk2(w4.y, w4.y);
        unsigned long long w2 = pk2(w4.z, w4.z), w3 = pk2(w4.w, w4.w);
#pragma unroll
        for (int p = 0; p < 4; p++){
            unsigned long long a = pk2(As[(ng+2*p)*96 + k], As[(ng+2*p+1)*96 + k]);
            ffma2(acc[p][0], a, w0); ffma2(acc[p][1], a, w1);
            ffma2(acc[p][2], a, w2); ffma2(acc[p][3], a, w3);
        }
    }
    float4 b4 = *(float4*)&bias[og];
#pragma unroll
    for (int p = 0; p < 4; p++){
        float lo[4], hi[4];
#pragma unroll
        for (int c = 0; c < 4; c++) upk2(acc[p][c], lo[c], hi[c]);
        float4 v0; v0.x = lo[0]+b4.x; v0.y = lo[1]+b4.y; v0.z = lo[2]+b4.z; v0.w = lo[3]+b4.w;
        float4 v1; v1.x = hi[0]+b4.x; v1.y = hi[1]+b4.y; v1.z = hi[2]+b4.z; v1.w = hi[3]+b4.w;
        *(float4*)&d_xbuf[(size_t)(nbase+ng+2*p  )*NF + og] = v0;
        *(float4*)&d_xbuf[(size_t)(nbase+ng+2*p+1)*NF + og] = v1;
    }
}

// ---------------- GIN aggregation: agg = x + sum_{j->i} x_j (per-graph CTA) ----------------
// lev selects edge buffers in DEVICE code: 0 -> raw input ei (EPG edges),
// 1 -> compacted A buffers, 2 -> compacted B buffers.
__global__ void __launch_bounds__(256) aggregate(int n, int lev,
        const int* __restrict__ ei){
    extern __shared__ float xs[];                 // n*128 floats
    __shared__ int cnt[256];
    __shared__ int wo[256];
    __shared__ int scan[256];
    __shared__ int rowptr[257];
    __shared__ int csr[EPG];
    int g = blockIdx.x, tid = threadIdx.x;
    const int* esrc; const int* edst; int m;
    if (lev == 0){ esrc = ei;     edst = ei + NE; m = EPG; }
    else if (lev == 1){ esrc = d_srcA; edst = d_dstA; m = d_ecntA[g]; }
    else              { esrc = d_srcB; edst = d_dstB; m = d_ecntB[g]; }
    float4* xs4 = (float4*)xs;
    const float4* xin4 = (const float4*)d_xbuf;
    for (int idx = tid; idx < n*32; idx += 256)
        xs4[idx] = xin4[(size_t)g*n*32 + idx];
    cnt[tid] = 0; wo[tid] = 0;
    __syncthreads();
    int ebase = g*EPG;
    int nodebase = g*n;
    for (int e = tid; e < m; e += 256)
        atomicAdd(&cnt[edst[ebase+e] - nodebase], 1);
    __syncthreads();
    // parallel inclusive scan over 256 entries
    scan[tid] = cnt[tid];
    __syncthreads();
#pragma unroll
    for (int off = 1; off < 256; off <<= 1){
        int v = (tid >= off) ? scan[tid-off] : 0;
        __syncthreads();
        scan[tid] += v;
        __syncthreads();
    }
    rowptr[tid+1] = scan[tid];
    if (tid == 0) rowptr[0] = 0;
    __syncthreads();
    for (int e = tid; e < m; e += 256){
        int d = edst[ebase+e] - nodebase;
        int pos = rowptr[d] + atomicAdd(&wo[d], 1);
        csr[pos] = esrc[ebase+e] - nodebase;
    }
    __syncthreads();
    int wid = tid >> 5, lane = tid & 31;
    float4* agg4 = (float4*)d_agg;
    for (int i = wid; i < n; i += 8){
        float4 acc = xs4[i*32 + lane];
        int p1 = rowptr[i+1];
        for (int p = rowptr[i]; p < p1; p++){
            float4 v = xs4[csr[p]*32 + lane];
            acc.x += v.x; acc.y += v.y; acc.z += v.z; acc.w += v.w;
        }
        agg4[(size_t)(nodebase + i)*32 + lane] = acc;
    }
}

// ---------------- fused KAN conv GEMM + relu: d_agg <- relu([A|B(A)] @ W), IN PLACE ----
// 128-node CTA tile, 8 rows x 8 outs per thread: 64B LDS per 64 FMA (1.0 B/FMA)
// balances the smem crossbar (128 B/cyc) against the fma pipe. R8-proven
// FFMA2 row-pair scheme. Safe in-place: CTA owns rows nb..nb+127; reads
// complete before the final barrier of the last chunk; writes after it.
__global__ void __launch_bounds__(256, 2) kan_gemm(int level){
    extern __shared__ float sm[];
    float* Et = sm;            // [KR][TN]   36 KB
    float* Ws = sm + KR*TN;    // [KR][128]  36 KB
    const float* __restrict__ W = d_wconvT + (size_t)level*KCONV*NF;
    int tid = threadIdx.x;
    int nb = blockIdx.x * TN;
    int ng = (tid >> 4) * 8;       // 16 row-groups of 8
    int og = (tid & 15) * 8;       // 16 out-groups of 8
    unsigned long long acc[4][8];  // 4 row-pairs x 8 outs
#pragma unroll
    for (int p = 0; p < 4; p++)
#pragma unroll
        for (int o = 0; o < 8; o++) acc[p][o] = 0ull;

    for (int c = 0; c < NF/CH; c++){
        int i0 = c*CH;
        __syncthreads();
        // expand TN nodes x CH inputs -> KR K-rows (lanes sweep nodes: conflict-free STS)
        for (int e = tid; e < TN*CH; e += 256){
            int nn = e & (TN-1), ii = e >> 7;
            float xv = d_agg[(size_t)(nb+nn)*NF + i0 + ii];
            float bs[8]; bsplines8(xv, bs);
            Et[(ii*9)*TN + nn] = xv;
#pragma unroll
            for (int s = 0; s < 8; s++) Et[(ii*9+1+s)*TN + nn] = bs[s];
        }
        {
            const float4* W4 = (const float4*)(W + (size_t)c*KR*128);
            float4* Ws4 = (float4*)Ws;
            for (int idx = tid; idx < KR*32; idx += 256)
                Ws4[idx] = W4[idx];
        }
        __syncthreads();
#pragma unroll 2
        for (int kk = 0; kk < KR; kk++){
            ulonglong2 a01 = *(const ulonglong2*)&Et[kk*TN + ng];      // rows ng..ng+3
            ulonglong2 a23 = *(const ulonglong2*)&Et[kk*TN + ng + 4];  // rows ng+4..ng+7
            float4 wa = *(const float4*)&Ws[kk*128 + og];
            float4 wb = *(const float4*)&Ws[kk*128 + og + 4];
            unsigned long long w0 = pk2(wa.x, wa.x), w1 = pk2(wa.y, wa.y);
            unsigned long long w2 = pk2(wa.z, wa.z), w3 = pk2(wa.w, wa.w);
            unsigned long long w4 = pk2(wb.x, wb.x), w5 = pk2(wb.y, wb.y);
            unsigned long long w6 = pk2(wb.z, wb.z), w7 = pk2(wb.w, wb.w);
            ffma2(acc[0][0], a01.x, w0); ffma2(acc[0][1], a01.x, w1);
            ffma2(acc[0][2], a01.x, w2); ffma2(acc[0][3], a01.x, w3);
            ffma2(acc[0][4], a01.x, w4); ffma2(acc[0][5], a01.x, w5);
            ffma2(acc[0][6], a01.x, w6); ffma2(acc[0][7], a01.x, w7);
            ffma2(acc[1][0], a01.y, w0); ffma2(acc[1][1], a01.y, w1);
            ffma2(acc[1][2], a01.y, w2); ffma2(acc[1][3], a01.y, w3);
            ffma2(acc[1][4], a01.y, w4); ffma2(acc[1][5], a01.y, w5);
            ffma2(acc[1][6], a01.y, w6); ffma2(acc[1][7], a01.y, w7);
            ffma2(acc[2][0], a23.x, w0); ffma2(acc[2][1], a23.x, w1);
            ffma2(acc[2][2], a23.x, w2); ffma2(acc[2][3], a23.x, w3);
            ffma2(acc[2][4], a23.x, w4); ffma2(acc[2][5], a23.x, w5);
            ffma2(acc[2][6], a23.x, w6); ffma2(acc[2][7], a23.x, w7);
            ffma2(acc[3][0], a23.y, w0); ffma2(acc[3][1], a23.y, w1);
            ffma2(acc[3][2], a23.y, w2); ffma2(acc[3][3], a23.y, w3);
            ffma2(acc[3][4], a23.y, w4); ffma2(acc[3][5], a23.y, w5);
            ffma2(acc[3][6], a23.y, w6); ffma2(acc[3][7], a23.y, w7);
        }
    }
#pragma unroll
    for (int p = 0; p < 4; p++){
        float lo[8], hi[8];
#pragma unroll
        for (int o = 0; o < 8; o++) upk2(acc[p][o], lo[o], hi[o]);
        float4 v0a, v0b, v1a, v1b;
        v0a.x = fmaxf(lo[0],0.f); v0a.y = fmaxf(lo[1],0.f); v0a.z = fmaxf(lo[2],0.f); v0a.w = fmaxf(lo[3],0.f);
        v0b.x = fmaxf(lo[4],0.f); v0b.y = fmaxf(lo[5],0.f); v0b.z = fmaxf(lo[6],0.f); v0b.w = fmaxf(lo[7],0.f);
        v1a.x = fmaxf(hi[0],0.f); v1a.y = fmaxf(hi[1],0.f); v1a.z = fmaxf(hi[2],0.f); v1a.w = fmaxf(hi[3],0.f);
        v1b.x = fmaxf(hi[4],0.f); v1b.y = fmaxf(hi[5],0.f); v1b.z = fmaxf(hi[6],0.f); v1b.w = fmaxf(hi[7],0.f);
        *(float4*)&d_agg[(size_t)(nb+ng+2*p  )*NF + og]     = v0a;
        *(float4*)&d_agg[(size_t)(nb+ng+2*p  )*NF + og + 4] = v0b;
        *(float4*)&d_agg[(size_t)(nb+ng+2*p+1)*NF + og]     = v1a;
        *(float4*)&d_agg[(size_t)(nb+ng+2*p+1)*NF + og + 4] = v1b;
    }
}

// ---------------- fused pool + edge-compact + readout (per-graph CTA) ----------------
// reads conv output from d_agg; writes gated survivors to d_xbuf; [gmp|gap] to d_read.
// lev selects edge buffers in DEVICE code: in: 0->ei, 1->A, 2->B; out: 0->A, 1->B, 2->none.
__global__ void __launch_bounds__(256) pool_fused(int n, int k, const float* __restrict__ p,
        int b, int lev, const int* __restrict__ ei){
    __shared__ float s[256];
    __shared__ int pos[256];
    __shared__ unsigned char kf[256];
    __shared__ int maxv[128];
    __shared__ float sumv[128];
    __shared__ int ecnt_s;
    int g = blockIdx.x, tid = threadIdx.x;
    int wid = tid >> 5, lane = tid & 31;
    int nodebase = g*n;
    const int* esrcIn; const int* edstIn; int m;
    if (lev == 0){ esrcIn = ei;     edstIn = ei + NE; m = EPG; }
    else if (lev == 1){ esrcIn = d_srcA; edstIn = d_dstA; m = d_ecntA[g]; }
    else              { esrcIn = d_srcB; edstIn = d_dstB; m = d_ecntB[g]; }
    for (int i = wid; i < n; i += 8){
        float v = 0.f;
#pragma unroll
        for (int t = 0; t < 4; t++){
            int f = lane + t*32;
            v += d_agg[(size_t)(nodebase+i)*NF + f] * p[f];
        }
#pragma unroll
        for (int o = 16; o > 0; o >>= 1) v += __shfl_down_sync(0xffffffffu, v, o);
        if (lane == 0) s[i] = 1.0f/(1.0f + expf(-v));
    }
    if (tid < 128){ maxv[tid] = 0; sumv[tid] = 0.f; }
    if (tid == 0) ecnt_s = 0;
    __syncthreads();
    for (int i = tid; i < n; i += 256){
        float si = s[i]; int c = 0;
        for (int j = 0; j < n; j++){
            float sj = s[j];
            c += (sj > si) || (sj == si && j < i);
        }
        kf[i] = (c < k) ? 1 : 0;
    }
    __syncthreads();
    for (int i = tid; i < n; i += 256){
        int c = 0;
        for (int j = 0; j < i; j++) c += kf[j];
        pos[i] = c;
    }
    __syncthreads();
    // gate + scatter + readout accumulation (values are >= 0: relu * sigmoid)
    for (int t = tid; t < n*NF; t += 256){
        int i = t >> 7, f = t & 127;
        if (kf[i]){
            float v = d_agg[(size_t)(nodebase+i)*NF + f] * s[i];
            d_xbuf[(size_t)(g*k + pos[i])*NF + f] = v;
            atomicMax(&maxv[f], __float_as_int(v));
            atomicAdd(&sumv[f], v);
        }
    }
    // edge remap + compact into output buffers (skip at last level: edges unused after)
    if (lev < 2){
        int ebase = g*EPG;
        int* esrcOut = (lev == 0) ? d_srcA : d_srcB;
        int* edstOut = (lev == 0) ? d_dstA : d_dstB;
        for (int e = tid; e < m; e += 256){
            int sN = esrcIn[ebase+e] - nodebase;
            int dN = edstIn[ebase+e] - nodebase;
            if (kf[sN] && kf[dN]){
                int slot = atomicAdd(&ecnt_s, 1);
                esrcOut[ebase+slot] = g*k + pos[sN];
                edstOut[ebase+slot] = g*k + pos[dN];
            }
        }
    }
    __syncthreads();
    if (tid < 128){
        float* o = &d_read[((size_t)(b*3+lev)*G + g)*256];
        o[tid] = __int_as_float(maxv[tid]);
        o[128 + tid] = sumv[tid] / (float)k;
    }
    if (tid == 0 && lev < 2){
        if (lev == 0) d_ecntA[g] = ecnt_s; else d_ecntB[g] = ecnt_s;
    }
}

// ---------------- head: combine readouts + fc_g KAN (256->256) ----------------
// grid (8 row-groups of 16, 2 output halves of 128)
__global__ void __launch_bounds__(256) head_fcg(int b, const float* __restrict__ wr,
                                                float* __restrict__ out){
    extern __shared__ float sm[];
    float* X  = sm;                 // [16][256]
    float* Et = sm + 16*256;        // [72][16]
    float* Ws = Et + 72*16;         // [72][128]
    int tid = threadIdx.x;
    int rb = blockIdx.x * 16;
    int ob = blockIdx.y * 128;
    float w0 = wr[0], w1 = wr[1], w2 = wr[2];
    for (int idx = tid; idx < 16*256; idx += 256){
        int r = idx >> 8, i = idx & 255;
        int row = rb + r;
        float v;
        if (b == 0){
            float a0 = d_read[((size_t)0*G + row)*256 + i];
            float a1 = d_read[((size_t)1*G + row)*256 + i];
            v = fmaxf(a0, 0.f) + fmaxf(a1, 0.f);
        } else {
            float a0 = d_read[((size_t)3*G + row)*256 + i];
            float a1 = d_read[((size_t)4*G + row)*256 + i];
            float a2 = d_read[((size_t)5*G + row)*256 + i];
            v = w0*fmaxf(a0, 0.f) + w1*fmaxf(a1, 0.f) + w2*fmaxf(a2, 0.f);
        }
        X[idx] = v;
    }
    const float* __restrict__ W = d_wfcgT + (size_t)b*KFC*256;
    int rg = (tid >> 5) * 2;       // 8 warps x 2 rows = 16 rows
    int og = (tid & 31) * 4;       // 128 outs
    unsigned long long acc[4];
#pragma unroll
    for (int c = 0; c < 4; c++) acc[c] = 0ull;

    for (int c = 0; c < 32; c++){
        int i0 = c*8;
        __syncthreads();
        if (tid < 128){
            int r = tid >> 3, ii = tid & 7;    // 16 rows x 8 inputs
            float xv = X[r*256 + i0 + ii];
            float bs[8]; bsplines8(xv, bs);
            Et[(ii*9)*16 + r] = xv;
#pragma unroll
            for (int s = 0; s < 8; s++) Et[(ii*9+1+s)*16 + r] = bs[s];
        }
        for (int idx = tid; idx < 72*128; idx += 256){
            int kk = idx >> 7, j = idx & 127;
            Ws[idx] = W[((size_t)c*72 + kk)*256 + ob + j];
        }
        __syncthreads();
#pragma unroll 4
        for (int kk = 0; kk < 72; kk++){
            unsigned long long a = *(const unsigned long long*)&Et[kk*16 + rg];
            float4 w4 = *(const float4*)&Ws[kk*128 + og];
            ffma2(acc[0], a, pk2(w4.x, w4.x));
            ffma2(acc[1], a, pk2(w4.y, w4.y));
            ffma2(acc[2], a, pk2(w4.z, w4.z));
            ffma2(acc[3], a, pk2(w4.w, w4.w));
        }
    }
    int outbase = 128 + b*(G*256);
    float lo[4], hi[4];
#pragma unroll
    for (int c = 0; c < 4; c++) upk2(acc[c], lo[c], hi[c]);
    int row0 = rb + rg, row1 = rb + rg + 1;
    float4 v0; v0.x = lo[0]; v0.y = lo[1]; v0.z = lo[2]; v0.w = lo[3];
    float4 v1; v1.x = hi[0]; v1.y = hi[1]; v1.z = hi[2]; v1.w = hi[3];
    *(float4*)&d_xg[((size_t)b*G + row0)*256 + ob + og] = v0;
    *(float4*)&d_xg[((size_t)b*G + row1)*256 + ob + og] = v1;
    *(float4*)&out[outbase + (size_t)row0*256 + ob + og] = v0;
    *(float4*)&out[outbase + (size_t)row1*256 + ob + og] = v1;
}

// ---------------- head: fc_final KAN (256->1) ----------------
__global__ void __launch_bounds__(256) head_fin(int b, float* __restrict__ out){
    __shared__ float Xs[256];
    __shared__ float red[256];
    int row = blockIdx.x, tid = threadIdx.x;
    Xs[tid] = d_xg[((size_t)b*G + row)*256 + tid];
    __syncthreads();
    float xv = Xs[tid];
    float bs[8]; bsplines8(xv, bs);
    const float* W = d_wfinT + (size_t)b*KFC + tid*9;
    float acc = xv * W[0];
#pragma unroll
    for (int s = 0; s < 8; s++) acc += bs[s]*W[1+s];
    red[tid] = acc;
    __syncthreads();
    for (int o = 128; o > 0; o >>= 1){
        if (tid < o) red[tid] += red[tid+o];
        __syncthreads();
    }
    if (tid == 0){
        int base = (b == 0) ? 0 : (128 + 2*G*256);   // z at 0, z1 at 65664
        out[base + row] = red[0];
    }
}

// ---------------- launch ----------------
extern "C" void kernel_launch(void* const* d_in, const int* in_sizes, int n_in,
                              void* d_out, int out_size){
    (void)in_sizes; (void)n_in; (void)out_size;
    const float* x       = (const float*)d_in[0];
    const float* a       = (const float*)d_in[1];
    const float* dt0_w   = (const float*)d_in[2];
    const float* dt0_b   = (const float*)d_in[3];
    const float* dt1_w   = (const float*)d_in[4];
    const float* dt1_b   = (const float*)d_in[5];
    const float* conv_bw = (const float*)d_in[6];
    const float* conv_sw = (const float*)d_in[7];
    const float* fcg_bw  = (const float*)d_in[8];
    const float* fcg_sw  = (const float*)d_in[9];
    const float* fin_bw  = (const float*)d_in[10];
    const float* fin_sw  = (const float*)d_in[11];
    const float* pool_p  = (const float*)d_in[12];
    const float* w_r     = (const float*)d_in[13];
    const int* edge_index = (const int*)d_in[14];
    const int* edge       = (const int*)d_in[15];
    float* out = (float*)d_out;

    cudaFuncSetAttribute(aggregate,    cudaFuncAttributeMaxDynamicSharedMemorySize, 256*128*4);
    cudaFuncSetAttribute(kan_gemm,     cudaFuncAttributeMaxDynamicSharedMemorySize, (KR*TN+KR*128)*4);
    cudaFuncSetAttribute(input_linear, cudaFuncAttributeMaxDynamicSharedMemorySize, (64*96+96*WSP)*4);
    cudaFuncSetAttribute(head_fcg,     cudaFuncAttributeMaxDynamicSharedMemorySize, (16*256+72*16+72*128)*4);

    // launch #1; keeps launch #4 == kan_gemm L0 so the profiler's fixed capture
    // slot lands on the GEMM.
    prep_conv<<<(6*KCONV*NF+255)/256, 256>>>(conv_bw, conv_sw);

    for (int b = 0; b < 2; b++){
        const float* feat = b ? a : x;
        int IN = b ? 43 : 93;
        const int* ei = b ? edge : edge_index;
        input_linear<<<NNODE/64, 256, (64*96+96*WSP)*4>>>(feat, b ? dt1_w : dt0_w,
                                                          b ? dt1_b : dt0_b, IN);
        int n = 256;
        for (int lev = 0; lev < 3; lev++){
            int l = b*3 + lev;
            int k = n/2;
            aggregate<<<G, 256, n*128*4>>>(n, lev, ei);
            kan_gemm<<<G*n/TN, 256, (KR*TN+KR*128)*4>>>(l);
            pool_fused<<<G, 256>>>(n, k, pool_p + l*NF, b, lev, ei);
            n = k;
        }
        if (b == 0){
            prep_fcg<<<(2*KFC*256+255)/256, 256>>>(fcg_bw, fcg_sw);
            prep_fin<<<(2*KFC+255)/256, 256>>>(fin_bw, fin_sw);
        }
        head_fcg<<<dim3(8,2), 256, (16*256+72*16+72*128)*4>>>(b, w_r, out);
        head_fin<<<G, 256>>>(b, out);
    }
}

// round 15
// speedup vs baseline: 1.3189x; 1.3189x over previous
#include <cuda_runtime.h>
#include <cuda_bf16.h>
#include <math.h>

#define G 128
#define NPG0 256
#define NNODE (G*NPG0)      // 32768
#define NF 128
#define EPG 4096
#define NE (G*EPG)          // 524288
#define KFC (256*9)         // 2304
#define WSP 132             // padded Ws stride in input_linear
#define TN 128              // nodes per kan CTA tile (M)
#define NCH 16              // K chunks: 8 inputs -> 72 real + 8 pad = 80 slots
#define ROWB 160            // bytes per A smem row (80 bf16)
// smem byte offsets for kan_gemm_mma
#define SM_AH 0
#define SM_AL 20480
#define SM_BH 40960
#define SM_BL 61440
#define SM_TOT 81920

// ---------------- scratch (device globals; no allocation) ----------------
// INVARIANT: referenced from DEVICE code only (host shadow-symbol UB lesson).
__device__ float d_xbuf[NNODE*NF];          // 16 MiB
__device__ float d_agg [NNODE*NF];          // 16 MiB (gemm writes back in place)
__device__ int   d_srcA[NE];
__device__ int   d_dstA[NE];
__device__ int   d_srcB[NE];
__device__ int   d_dstB[NE];
__device__ int   d_ecntA[G];
__device__ int   d_ecntB[G];
__device__ float d_read[2*3*G*256];
// B fragments: [6][2 terms][16 chunks][5 ksteps][16 ntiles][32 lanes][2 regs] u32
__device__ unsigned d_wcb[6*2*16*5*16*64]; // 3.75 MiB
__device__ float d_wfcgT[2*KFC*256];        // 4.5 MiB
__device__ float d_wfinT[2*KFC];
__device__ float d_xg[2*G*256];

// ---------------- packed f32x2 helpers ----------------
__device__ __forceinline__ unsigned long long pk2(float lo, float hi){
    unsigned long long r;
    asm("mov.b64 %0, {%1, %2};" : "=l"(r) : "f"(lo), "f"(hi));
    return r;
}
__device__ __forceinline__ void upk2(unsigned long long v, float& lo, float& hi){
    asm("mov.b64 {%0, %1}, %2;" : "=f"(lo), "=f"(hi) : "l"(v));
}
__device__ __forceinline__ void ffma2(unsigned long long& acc, unsigned long long a,
                                      unsigned long long b){
    asm("fma.rn.f32x2 %0, %1, %2, %0;" : "+l"(acc) : "l"(a), "l"(b));
}

// ---------------- bf16 mma.sync m16n8k16 (base PTX, compiles on sm_100) ----------------
__device__ __forceinline__ void mma16816(float* c, const unsigned* a,
                                         unsigned b0, unsigned b1){
    asm volatile("mma.sync.aligned.m16n8k16.row.col.f32.bf16.bf16.f32 "
        "{%0,%1,%2,%3}, {%4,%5,%6,%7}, {%8,%9}, {%0,%1,%2,%3};"
        : "+f"(c[0]), "+f"(c[1]), "+f"(c[2]), "+f"(c[3])
        : "r"(a[0]), "r"(a[1]), "r"(a[2]), "r"(a[3]), "r"(b0), "r"(b1));
}

// ---------------- B-spline basis (cubic, GRID=5, 8 outputs) ----------------
__device__ __forceinline__ float knot(int j){ return (float)(j-3)*0.4f - 1.0f; }

__device__ __forceinline__ void bsplines8(float x, float* out){
    float b[11];
#pragma unroll
    for (int j = 0; j < 11; j++){
        float g0 = knot(j), g1 = knot(j+1);
        b[j] = (x >= g0 && x < g1) ? 1.0f : 0.0f;
    }
#pragma unroll
    for (int k = 1; k <= 3; k++){
#pragma unroll
        for (int j = 0; j <= 10-k; j++){
            float gj  = knot(j),     gjk  = knot(j+k);
            float gj1 = knot(j+1),   gjk1 = knot(j+k+1);
            b[j] = (x - gj)*(1.0f/(gjk - gj))*b[j]
                 + (gjk1 - x)*(1.0f/(gjk1 - gj1))*b[j+1];
        }
    }
#pragma unroll
    for (int j = 0; j < 8; j++) out[j] = b[j];
}

// ---------------- weight prep: pack conv weights into mma B-fragment layout ----------------
// One u32 per thread = 2 bf16 (k even/odd). Hi term t=0, lo term t=1.
__global__ void prep_w_mma(const float* __restrict__ bw, const float* __restrict__ sw){
    int idx = blockIdx.x*blockDim.x + threadIdx.x;
    if (idx >= 6*2*16*5*16*64) return;
    int r    = idx & 1;
    int lane = (idx >> 1) & 31;
    int nt   = (idx >> 6) & 15;
    int ks   = (idx >> 10) % 5;
    int c    = (idx / 5120) & 15;
    int t    = (idx / 81920) % 2;
    int l    = idx / 163840;
    int n = nt*8 + (lane >> 2);
    int slot0 = ks*16 + (lane & 3)*2 + r*8;
    unsigned out = 0;
#pragma unroll
    for (int e = 0; e < 2; e++){
        int slot = slot0 + e;
        float v = 0.f;
        if (slot < 72){
            int k = c*72 + slot;
            int i = k / 9, s = k % 9;
            v = (s == 0) ? bw[(l*NF + n)*NF + i]
                         : sw[((l*NF + n)*NF + i)*8 + (s-1)];
        }
        __nv_bfloat16 vh = __float2bfloat16(v);
        unsigned short bits;
        if (t == 0) bits = __bfloat16_as_ushort(vh);
        else        bits = __bfloat16_as_ushort(__float2bfloat16(v - __bfloat162float(vh)));
        out |= ((unsigned)bits) << (16*e);
    }
    d_wcb[idx] = out;
}
__global__ void prep_fcg(const float* __restrict__ bw, const float* __restrict__ sw){
    int idx = blockIdx.x*blockDim.x + threadIdx.x;
    if (idx >= 2*KFC*256) return;
    int o = idx % 256;
    int kk = (idx / 256) % KFC;
    int l = idx / (256*KFC);
    int i = kk / 9, s = kk % 9;
    float v = (s==0) ? bw[(l*256 + o)*256 + i]
                     : sw[((l*256 + o)*256 + i)*8 + (s-1)];
    d_wfcgT[idx] = v;
}
__global__ void prep_fin(const float* __restrict__ bw, const float* __restrict__ sw){
    int idx = blockIdx.x*blockDim.x + threadIdx.x;
    if (idx >= 2*KFC) return;
    int kk = idx % KFC;
    int l = idx / KFC;
    int i = kk / 9, s = kk % 9;
    float v = (s==0) ? bw[l*256 + i] : sw[(l*256 + i)*8 + (s-1)];
    d_wfinT[idx] = v;
}

// ---------------- input linear: x = feat @ w.T + b -> d_xbuf ----------------
__global__ void __launch_bounds__(256) input_linear(
        const float* __restrict__ feat, const float* __restrict__ w,
        const float* __restrict__ bias, int IN){
    extern __shared__ float sm[];
    float* As = sm;              // [64][96]
    float* Ws = sm + 64*96;      // [96][WSP]
    int tid = threadIdx.x;
    int nbase = blockIdx.x * 64;
    for (int idx = tid; idx < 64*IN; idx += 256){
        int n = idx / IN, i = idx % IN;
        As[n*96 + i] = feat[(size_t)(nbase+n)*IN + i];
    }
    for (int idx = tid; idx < NF*IN; idx += 256){
        int o = idx / IN, i = idx % IN;
        Ws[i*WSP + o] = w[idx];
    }
    __syncthreads();
    int ng = (tid >> 5) * 8;
    int og = (tid & 31) * 4;
    unsigned long long acc[4][4];
#pragma unroll
    for (int p = 0; p < 4; p++)
#pragma unroll
        for (int c = 0; c < 4; c++) acc[p][c] = 0ull;
    for (int k = 0; k < IN; k++){
        float4 w4 = *(float4*)&Ws[k*WSP + og];
        unsigned long long w0 = pk2(w4.x, w4.x), w1 = pk2(w4.y, w4.y);
        unsigned long long w2 = pk2(w4.z, w4.z), w3 = pk2(w4.w, w4.w);
#pragma unroll
        for (int p = 0; p < 4; p++){
            unsigned long long a = pk2(As[(ng+2*p)*96 + k], As[(ng+2*p+1)*96 + k]);
            ffma2(acc[p][0], a, w0); ffma2(acc[p][1], a, w1);
            ffma2(acc[p][2], a, w2); ffma2(acc[p][3], a, w3);
        }
    }
    float4 b4 = *(float4*)&bias[og];
#pragma unroll
    for (int p = 0; p < 4; p++){
        float lo[4], hi[4];
#pragma unroll
        for (int c = 0; c < 4; c++) upk2(acc[p][c], lo[c], hi[c]);
        float4 v0; v0.x = lo[0]+b4.x; v0.y = lo[1]+b4.y; v0.z = lo[2]+b4.z; v0.w = lo[3]+b4.w;
        float4 v1; v1.x = hi[0]+b4.x; v1.y = hi[1]+b4.y; v1.z = hi[2]+b4.z; v1.w = hi[3]+b4.w;
        *(float4*)&d_xbuf[(size_t)(nbase+ng+2*p  )*NF + og] = v0;
        *(float4*)&d_xbuf[(size_t)(nbase+ng+2*p+1)*NF + og] = v1;
    }
}

// ---------------- GIN aggregation (per-graph CTA) ----------------
__global__ void __launch_bounds__(256) aggregate(int n, int lev,
        const int* __restrict__ ei){
    extern __shared__ float xs[];
    __shared__ int cnt[256];
    __shared__ int wo[256];
    __shared__ int scan[256];
    __shared__ int rowptr[257];
    __shared__ int csr[EPG];
    int g = blockIdx.x, tid = threadIdx.x;
    const int* esrc; const int* edst; int m;
    if (lev == 0){ esrc = ei;     edst = ei + NE; m = EPG; }
    else if (lev == 1){ esrc = d_srcA; edst = d_dstA; m = d_ecntA[g]; }
    else              { esrc = d_srcB; edst = d_dstB; m = d_ecntB[g]; }
    float4* xs4 = (float4*)xs;
    const float4* xin4 = (const float4*)d_xbuf;
    for (int idx = tid; idx < n*32; idx += 256)
        xs4[idx] = xin4[(size_t)g*n*32 + idx];
    cnt[tid] = 0; wo[tid] = 0;
    __syncthreads();
    int ebase = g*EPG;
    int nodebase = g*n;
    for (int e = tid; e < m; e += 256)
        atomicAdd(&cnt[edst[ebase+e] - nodebase], 1);
    __syncthreads();
    scan[tid] = cnt[tid];
    __syncthreads();
#pragma unroll
    for (int off = 1; off < 256; off <<= 1){
        int v = (tid >= off) ? scan[tid-off] : 0;
        __syncthreads();
        scan[tid] += v;
        __syncthreads();
    }
    rowptr[tid+1] = scan[tid];
    if (tid == 0) rowptr[0] = 0;
    __syncthreads();
    for (int e = tid; e < m; e += 256){
        int d = edst[ebase+e] - nodebase;
        int pos = rowptr[d] + atomicAdd(&wo[d], 1);
        csr[pos] = esrc[ebase+e] - nodebase;
    }
    __syncthreads();
    int wid = tid >> 5, lane = tid & 31;
    float4* agg4 = (float4*)d_agg;
    for (int i = wid; i < n; i += 8){
        float4 acc = xs4[i*32 + lane];
        int p1 = rowptr[i+1];
        for (int p = rowptr[i]; p < p1; p++){
            float4 v = xs4[csr[p]*32 + lane];
            acc.x += v.x; acc.y += v.y; acc.z += v.z; acc.w += v.w;
        }
        agg4[(size_t)(nodebase + i)*32 + lane] = acc;
    }
}

// ---------------- bf16 HMMA KAN conv GEMM + relu, IN PLACE on d_agg ----------------
// D[128 nodes][128 outs] = [A|B(A)] @ W via mma.sync m16n8k16 bf16,
// hi/lo split 3 terms. K chunked: 8 inputs -> 80 slots (72 real + 8 zero pad).
// Accumulate fp32 in registers across 16 chunks. B pre-packed in frag layout.
__global__ void __launch_bounds__(256, 2) kan_gemm_mma(int level){
    extern __shared__ char smraw[];
    unsigned short* AHs = (unsigned short*)(smraw + SM_AH);  // [128][80] bf16
    unsigned short* ALs = (unsigned short*)(smraw + SM_AL);
    unsigned* BH = (unsigned*)(smraw + SM_BH);               // [5][16][64] u32
    unsigned* BL = (unsigned*)(smraw + SM_BL);
    int tid = threadIdx.x;
    int w = tid >> 5, lane = tid & 31;
    int gid = lane >> 2, tig = lane & 3;
    int nb = blockIdx.x * TN;
    int M0 = (w & 3) * 32;         // 4 warps over M
    int NT0 = (w >> 2) * 8;        // 2 warps over N (8 ntiles each)

    float cacc[2][8][4];
#pragma unroll
    for (int mf = 0; mf < 2; mf++)
#pragma unroll
        for (int nf = 0; nf < 8; nf++)
#pragma unroll
            for (int q = 0; q < 4; q++) cacc[mf][nf][q] = 0.f;

    for (int c = 0; c < NCH; c++){
        // ---- expansion: 128 nodes x 8 inputs -> AH/AL bf16 slots ----
        for (int t = tid; t < TN*8; t += 256){
            int nn = t >> 3, ii = t & 7;
            float xv = d_agg[(size_t)(nb+nn)*NF + c*8 + ii];
            float bs[8]; bsplines8(xv, bs);
            float v[9];
            v[0] = xv;
#pragma unroll
            for (int s = 0; s < 8; s++) v[1+s] = bs[s];
            unsigned short* dh = &AHs[nn*80 + ii*9];
            unsigned short* dl = &ALs[nn*80 + ii*9];
#pragma unroll
            for (int q = 0; q < 9; q++){
                __nv_bfloat16 h = __float2bfloat16(v[q]);
                dh[q] = __bfloat16_as_ushort(h);
                dl[q] = __bfloat16_as_ushort(__float2bfloat16(v[q] - __bfloat162float(h)));
            }
        }
        // zero pad slots 72..79 (16B per row)
        if (tid < 128){
            uint4 z = {0,0,0,0};
            *(uint4*)(smraw + SM_AH + tid*ROWB + 144) = z;
            *(uint4*)(smraw + SM_AL + tid*ROWB + 144) = z;
        }
        // ---- copy B fragment chunk (both terms), linear/coalesced ----
        {
            const float4* sh = (const float4*)(d_wcb + ((size_t)(level*2+0)*NCH + c)*5120);
            const float4* sl = (const float4*)(d_wcb + ((size_t)(level*2+1)*NCH + c)*5120);
            float4* bh4 = (float4*)BH;
            float4* bl4 = (float4*)BL;
            for (int i = tid; i < 1280; i += 256){
                bh4[i] = sh[i];
                bl4[i] = sl[i];
            }
        }
        __syncthreads();
        // ---- MMA: 5 ksteps x (2 mfrags x 8 ntiles x 3 terms) ----
#pragma unroll
        for (int ks = 0; ks < 5; ks++){
            unsigned aH[2][4], aL[2][4];
#pragma unroll
            for (int mf = 0; mf < 2; mf++){
                int r0 = M0 + mf*16 + gid;
                int bo = ks*32 + tig*4;
                aH[mf][0] = *(const unsigned*)(smraw + SM_AH + r0*ROWB + bo);
                aH[mf][1] = *(const unsigned*)(smraw + SM_AH + (r0+8)*ROWB + bo);
                aH[mf][2] = *(const unsigned*)(smraw + SM_AH + r0*ROWB + bo + 16);
                aH[mf][3] = *(const unsigned*)(smraw + SM_AH + (r0+8)*ROWB + bo + 16);
                aL[mf][0] = *(const unsigned*)(smraw + SM_AL + r0*ROWB + bo);
                aL[mf][1] = *(const unsigned*)(smraw + SM_AL + (r0+8)*ROWB + bo);
                aL[mf][2] = *(const unsigned*)(smraw + SM_AL + r0*ROWB + bo + 16);
                aL[mf][3] = *(const unsigned*)(smraw + SM_AL + (r0+8)*ROWB + bo + 16);
            }
#pragma unroll
            for (int nf = 0; nf < 8; nf++){
                int bi = (ks*16 + NT0 + nf)*64 + lane*2;
                unsigned bh0 = BH[bi], bh1 = BH[bi+1];
                unsigned bl0 = BL[bi], bl1 = BL[bi+1];
#pragma unroll
                for (int mf = 0; mf < 2; mf++){
                    mma16816(cacc[mf][nf], aH[mf], bh0, bh1);
                    mma16816(cacc[mf][nf], aH[mf], bl0, bl1);
                    mma16816(cacc[mf][nf], aL[mf], bh0, bh1);
                }
            }
        }
        __syncthreads();   // protect smem before next chunk's expansion
    }
    // ---- writeback with relu (in place; all reads of d_agg completed) ----
#pragma unroll
    for (int mf = 0; mf < 2; mf++){
#pragma unroll
        for (int nf = 0; nf < 8; nf++){
            int row0 = nb + M0 + mf*16 + gid;
            int col = NT0*8 + nf*8 + tig*2;
            float2 v0; v0.x = fmaxf(cacc[mf][nf][0], 0.f); v0.y = fmaxf(cacc[mf][nf][1], 0.f);
            float2 v1; v1.x = fmaxf(cacc[mf][nf][2], 0.f); v1.y = fmaxf(cacc[mf][nf][3], 0.f);
            *(float2*)&d_agg[(size_t)row0*NF + col] = v0;
            *(float2*)&d_agg[(size_t)(row0+8)*NF + col] = v1;
        }
    }
}

// ---------------- fused pool + edge-compact + readout (per-graph CTA) ----------------
__global__ void __launch_bounds__(256) pool_fused(int n, int k, const float* __restrict__ p,
        int b, int lev, const int* __restrict__ ei){
    __shared__ float s[256];
    __shared__ int pos[256];
    __shared__ unsigned char kf[256];
    __shared__ int maxv[128];
    __shared__ float sumv[128];
    __shared__ int ecnt_s;
    int g = blockIdx.x, tid = threadIdx.x;
    int wid = tid >> 5, lane = tid & 31;
    int nodebase = g*n;
    const int* esrcIn; const int* edstIn; int m;
    if (lev == 0){ esrcIn = ei;     edstIn = ei + NE; m = EPG; }
    else if (lev == 1){ esrcIn = d_srcA; edstIn = d_dstA; m = d_ecntA[g]; }
    else              { esrcIn = d_srcB; edstIn = d_dstB; m = d_ecntB[g]; }
    for (int i = wid; i < n; i += 8){
        float v = 0.f;
#pragma unroll
        for (int t = 0; t < 4; t++){
            int f = lane + t*32;
            v += d_agg[(size_t)(nodebase+i)*NF + f] * p[f];
        }
#pragma unroll
        for (int o = 16; o > 0; o >>= 1) v += __shfl_down_sync(0xffffffffu, v, o);
        if (lane == 0) s[i] = 1.0f/(1.0f + expf(-v));
    }
    if (tid < 128){ maxv[tid] = 0; sumv[tid] = 0.f; }
    if (tid == 0) ecnt_s = 0;
    __syncthreads();
    for (int i = tid; i < n; i += 256){
        float si = s[i]; int c = 0;
        for (int j = 0; j < n; j++){
            float sj = s[j];
            c += (sj > si) || (sj == si && j < i);
        }
        kf[i] = (c < k) ? 1 : 0;
    }
    __syncthreads();
    for (int i = tid; i < n; i += 256){
        int c = 0;
        for (int j = 0; j < i; j++) c += kf[j];
        pos[i] = c;
    }
    __syncthreads();
    for (int t = tid; t < n*NF; t += 256){
        int i = t >> 7, f = t & 127;
        if (kf[i]){
            float v = d_agg[(size_t)(nodebase+i)*NF + f] * s[i];
            d_xbuf[(size_t)(g*k + pos[i])*NF + f] = v;
            atomicMax(&maxv[f], __float_as_int(v));
            atomicAdd(&sumv[f], v);
        }
    }
    if (lev < 2){
        int ebase = g*EPG;
        int* esrcOut = (lev == 0) ? d_srcA : d_srcB;
        int* edstOut = (lev == 0) ? d_dstA : d_dstB;
        for (int e = tid; e < m; e += 256){
            int sN = esrcIn[ebase+e] - nodebase;
            int dN = edstIn[ebase+e] - nodebase;
            if (kf[sN] && kf[dN]){
                int slot = atomicAdd(&ecnt_s, 1);
                esrcOut[ebase+slot] = g*k + pos[sN];
                edstOut[ebase+slot] = g*k + pos[dN];
            }
        }
    }
    __syncthreads();
    if (tid < 128){
        float* o = &d_read[((size_t)(b*3+lev)*G + g)*256];
        o[tid] = __int_as_float(maxv[tid]);
        o[128 + tid] = sumv[tid] / (float)k;
    }
    if (tid == 0 && lev < 2){
        if (lev == 0) d_ecntA[g] = ecnt_s; else d_ecntB[g] = ecnt_s;
    }
}

// ---------------- head: combine readouts + fc_g KAN (256->256) ----------------
__global__ void __launch_bounds__(256) head_fcg(int b, const float* __restrict__ wr,
                                                float* __restrict__ out){
    extern __shared__ float sm[];
    float* X  = sm;                 // [16][256]
    float* Et = sm + 16*256;        // [72][16]
    float* Ws = Et + 72*16;         // [72][128]
    int tid = threadIdx.x;
    int rb = blockIdx.x * 16;
    int ob = blockIdx.y * 128;
    float w0 = wr[0], w1 = wr[1], w2 = wr[2];
    for (int idx = tid; idx < 16*256; idx += 256){
        int r = idx >> 8, i = idx & 255;
        int row = rb + r;
        float v;
        if (b == 0){
            float a0 = d_read[((size_t)0*G + row)*256 + i];
            float a1 = d_read[((size_t)1*G + row)*256 + i];
            v = fmaxf(a0, 0.f) + fmaxf(a1, 0.f);
        } else {
            float a0 = d_read[((size_t)3*G + row)*256 + i];
            float a1 = d_read[((size_t)4*G + row)*256 + i];
            float a2 = d_read[((size_t)5*G + row)*256 + i];
            v = w0*fmaxf(a0, 0.f) + w1*fmaxf(a1, 0.f) + w2*fmaxf(a2, 0.f);
        }
        X[idx] = v;
    }
    const float* __restrict__ W = d_wfcgT + (size_t)b*KFC*256;
    int rg = (tid >> 5) * 2;
    int og = (tid & 31) * 4;
    unsigned long long acc[4];
#pragma unroll
    for (int c = 0; c < 4; c++) acc[c] = 0ull;

    for (int c = 0; c < 32; c++){
        int i0 = c*8;
        __syncthreads();
        if (tid < 128){
            int r = tid >> 3, ii = tid & 7;
            float xv = X[r*256 + i0 + ii];
            float bs[8]; bsplines8(xv, bs);
            Et[(ii*9)*16 + r] = xv;
#pragma unroll
            for (int s = 0; s < 8; s++) Et[(ii*9+1+s)*16 + r] = bs[s];
        }
        for (int idx = tid; idx < 72*128; idx += 256){
            int kk = idx >> 7, j = idx & 127;
            Ws[idx] = W[((size_t)c*72 + kk)*256 + ob + j];
        }
        __syncthreads();
#pragma unroll 4
        for (int kk = 0; kk < 72; kk++){
            unsigned long long a = *(const unsigned long long*)&Et[kk*16 + rg];
            float4 w4 = *(const float4*)&Ws[kk*128 + og];
            ffma2(acc[0], a, pk2(w4.x, w4.x));
            ffma2(acc[1], a, pk2(w4.y, w4.y));
            ffma2(acc[2], a, pk2(w4.z, w4.z));
            ffma2(acc[3], a, pk2(w4.w, w4.w));
        }
    }
    int outbase = 128 + b*(G*256);
    float lo[4], hi[4];
#pragma unroll
    for (int c = 0; c < 4; c++) upk2(acc[c], lo[c], hi[c]);
    int row0 = rb + rg, row1 = rb + rg + 1;
    float4 v0; v0.x = lo[0]; v0.y = lo[1]; v0.z = lo[2]; v0.w = lo[3];
    float4 v1; v1.x = hi[0]; v1.y = hi[1]; v1.z = hi[2]; v1.w = hi[3];
    *(float4*)&d_xg[((size_t)b*G + row0)*256 + ob + og] = v0;
    *(float4*)&d_xg[((size_t)b*G + row1)*256 + ob + og] = v1;
    *(float4*)&out[outbase + (size_t)row0*256 + ob + og] = v0;
    *(float4*)&out[outbase + (size_t)row1*256 + ob + og] = v1;
}

// ---------------- head: fc_final KAN (256->1) ----------------
__global__ void __launch_bounds__(256) head_fin(int b, float* __restrict__ out){
    __shared__ float Xs[256];
    __shared__ float red[256];
    int row = blockIdx.x, tid = threadIdx.x;
    Xs[tid] = d_xg[((size_t)b*G + row)*256 + tid];
    __syncthreads();
    float xv = Xs[tid];
    float bs[8]; bsplines8(xv, bs);
    const float* W = d_wfinT + (size_t)b*KFC + tid*9;
    float acc = xv * W[0];
#pragma unroll
    for (int s = 0; s < 8; s++) acc += bs[s]*W[1+s];
    red[tid] = acc;
    __syncthreads();
    for (int o = 128; o > 0; o >>= 1){
        if (tid < o) red[tid] += red[tid+o];
        __syncthreads();
    }
    if (tid == 0){
        int base = (b == 0) ? 0 : (128 + 2*G*256);
        out[base + row] = red[0];
    }
}

// ---------------- launch ----------------
extern "C" void kernel_launch(void* const* d_in, const int* in_sizes, int n_in,
                              void* d_out, int out_size){
    (void)in_sizes; (void)n_in; (void)out_size;
    const float* x       = (const float*)d_in[0];
    const float* a       = (const float*)d_in[1];
    const float* dt0_w   = (const float*)d_in[2];
    const float* dt0_b   = (const float*)d_in[3];
    const float* dt1_w   = (const float*)d_in[4];
    const float* dt1_b   = (const float*)d_in[5];
    const float* conv_bw = (const float*)d_in[6];
    const float* conv_sw = (const float*)d_in[7];
    const float* fcg_bw  = (const float*)d_in[8];
    const float* fcg_sw  = (const float*)d_in[9];
    const float* fin_bw  = (const float*)d_in[10];
    const float* fin_sw  = (const float*)d_in[11];
    const float* pool_p  = (const float*)d_in[12];
    const float* w_r     = (const float*)d_in[13];
    const int* edge_index = (const int*)d_in[14];
    const int* edge       = (const int*)d_in[15];
    float* out = (float*)d_out;

    cudaFuncSetAttribute(aggregate,    cudaFuncAttributeMaxDynamicSharedMemorySize, 256*128*4);
    cudaFuncSetAttribute(kan_gemm_mma, cudaFuncAttributeMaxDynamicSharedMemorySize, SM_TOT);
    cudaFuncSetAttribute(input_linear, cudaFuncAttributeMaxDynamicSharedMemorySize, (64*96+96*WSP)*4);
    cudaFuncSetAttribute(head_fcg,     cudaFuncAttributeMaxDynamicSharedMemorySize, (16*256+72*16+72*128)*4);

    // launch #1; keeps launch #4 == kan_gemm_mma L0 in the profiler capture slot.
    prep_w_mma<<<(6*2*16*5*16*64+255)/256, 256>>>(conv_bw, conv_sw);

    for (int b = 0; b < 2; b++){
        const float* feat = b ? a : x;
        int IN = b ? 43 : 93;
        const int* ei = b ? edge : edge_index;
        input_linear<<<NNODE/64, 256, (64*96+96*WSP)*4>>>(feat, b ? dt1_w : dt0_w,
                                                          b ? dt1_b : dt0_b, IN);
        int n = 256;
        for (int lev = 0; lev < 3; lev++){
            int l = b*3 + lev;
            int k = n/2;
            aggregate<<<G, 256, n*128*4>>>(n, lev, ei);
            kan_gemm_mma<<<G*n/TN, 256, SM_TOT>>>(l);
            pool_fused<<<G, 256>>>(n, k, pool_p + l*NF, b, lev, ei);
            n = k;
        }
        if (b == 0){
            prep_fcg<<<(2*KFC*256+255)/256, 256>>>(fcg_bw, fcg_sw);
            prep_fin<<<(2*KFC+255)/256, 256>>>(fin_bw, fin_sw);
        }
        head_fcg<<<dim3(8,2), 256, (16*256+72*16+72*128)*4>>>(b, w_r, out);
        head_fin<<<G, 256>>>(b, out);
    }
}

// round 16
// speedup vs baseline: 1.6780x; 1.2723x over previous
#include <cuda_runtime.h>
#include <cuda_bf16.h>
#include <math.h>

#define G 128
#define NPG0 256
#define NNODE (G*NPG0)      // 32768
#define NF 128
#define EPG 4096
#define EPG2 (EPG/2)        // per-graph compacted edge capacity
#define NE (G*EPG)          // 524288
#define NE2 (G*EPG2)
#define KFC (256*9)         // 2304
#define WSP 132             // padded Ws stride in input_linear
#define TN 128              // nodes per kan CTA tile (M)
#define NCH 16              // K chunks: 8 inputs -> 72 real + 8 pad = 80 slots
#define ROWB 160            // bytes per A smem row (80 bf16)
// smem byte offsets for kan_gemm_mma
#define SM_AH 0
#define SM_AL 20480
#define SM_BH 40960
#define SM_BL 61440
#define SM_TOT 81920

// ---------------- scratch (device globals; no allocation) ----------------
// INVARIANT: referenced from DEVICE code only (host shadow-symbol UB lesson).
// Branch-merged pipeline: features carry a [2] branch dimension.
__device__ float d_xbuf[2][NNODE*NF];       // 32 MiB
__device__ float d_agg [2][NNODE*NF];       // 32 MiB (gemm in place)
__device__ int   d_srcA[2][NE2];            // 8 MiB total edge ping-pong
__device__ int   d_dstA[2][NE2];
__device__ int   d_srcB[2][NE2];
__device__ int   d_dstB[2][NE2];
__device__ int   d_ecntA[2*G];
__device__ int   d_ecntB[2*G];
__device__ float d_read[2*3*G*256];
// B fragments: [6][2 terms][16 chunks][5 ksteps][16 ntiles][32 lanes][2 regs] u32
__device__ unsigned d_wcb[6*2*16*5*16*64];  // 3.75 MiB
__device__ float d_wfcgT[2*KFC*256];        // 4.5 MiB
__device__ float d_wfinT[2*KFC];
__device__ float d_xg[2*G*256];

// ---------------- packed f32x2 helpers ----------------
__device__ __forceinline__ unsigned long long pk2(float lo, float hi){
    unsigned long long r;
    asm("mov.b64 %0, {%1, %2};" : "=l"(r) : "f"(lo), "f"(hi));
    return r;
}
__device__ __forceinline__ void upk2(unsigned long long v, float& lo, float& hi){
    asm("mov.b64 {%0, %1}, %2;" : "=f"(lo), "=f"(hi) : "l"(v));
}
__device__ __forceinline__ void ffma2(unsigned long long& acc, unsigned long long a,
                                      unsigned long long b){
    asm("fma.rn.f32x2 %0, %1, %2, %0;" : "+l"(acc) : "l"(a), "l"(b));
}

// ---------------- bf16 mma.sync m16n8k16 (base PTX) ----------------
__device__ __forceinline__ void mma16816(float* c, const unsigned* a,
                                         unsigned b0, unsigned b1){
    asm volatile("mma.sync.aligned.m16n8k16.row.col.f32.bf16.bf16.f32 "
        "{%0,%1,%2,%3}, {%4,%5,%6,%7}, {%8,%9}, {%0,%1,%2,%3};"
        : "+f"(c[0]), "+f"(c[1]), "+f"(c[2]), "+f"(c[3])
        : "r"(a[0]), "r"(a[1]), "r"(a[2]), "r"(a[3]), "r"(b0), "r"(b1));
}

// ---------------- B-spline basis (cubic, GRID=5, 8 outputs) ----------------
__device__ __forceinline__ float knot(int j){ return (float)(j-3)*0.4f - 1.0f; }

__device__ __forceinline__ void bsplines8(float x, float* out){
    float b[11];
#pragma unroll
    for (int j = 0; j < 11; j++){
        float g0 = knot(j), g1 = knot(j+1);
        b[j] = (x >= g0 && x < g1) ? 1.0f : 0.0f;
    }
#pragma unroll
    for (int k = 1; k <= 3; k++){
#pragma unroll
        for (int j = 0; j <= 10-k; j++){
            float gj  = knot(j),     gjk  = knot(j+k);
            float gj1 = knot(j+1),   gjk1 = knot(j+k+1);
            b[j] = (x - gj)*(1.0f/(gjk - gj))*b[j]
                 + (gjk1 - x)*(1.0f/(gjk1 - gj1))*b[j+1];
        }
    }
#pragma unroll
    for (int j = 0; j < 8; j++) out[j] = b[j];
}

// ---------------- weight prep: pack conv weights into mma B-fragment layout ----------------
__global__ void prep_w_mma(const float* __restrict__ bw, const float* __restrict__ sw){
    int idx = blockIdx.x*blockDim.x + threadIdx.x;
    if (idx >= 6*2*16*5*16*64) return;
    int r    = idx & 1;
    int lane = (idx >> 1) & 31;
    int nt   = (idx >> 6) & 15;
    int ks   = (idx >> 10) % 5;
    int c    = (idx / 5120) & 15;
    int t    = (idx / 81920) % 2;
    int l    = idx / 163840;
    int n = nt*8 + (lane >> 2);
    int slot0 = ks*16 + (lane & 3)*2 + r*8;
    unsigned out = 0;
#pragma unroll
    for (int e = 0; e < 2; e++){
        int slot = slot0 + e;
        float v = 0.f;
        if (slot < 72){
            int k = c*72 + slot;
            int i = k / 9, s = k % 9;
            v = (s == 0) ? bw[(l*NF + n)*NF + i]
                         : sw[((l*NF + n)*NF + i)*8 + (s-1)];
        }
        __nv_bfloat16 vh = __float2bfloat16(v);
        unsigned short bits;
        if (t == 0) bits = __bfloat16_as_ushort(vh);
        else        bits = __bfloat16_as_ushort(__float2bfloat16(v - __bfloat162float(vh)));
        out |= ((unsigned)bits) << (16*e);
    }
    d_wcb[idx] = out;
}
__global__ void prep_fcg(const float* __restrict__ bw, const float* __restrict__ sw){
    int idx = blockIdx.x*blockDim.x + threadIdx.x;
    if (idx >= 2*KFC*256) return;
    int o = idx % 256;
    int kk = (idx / 256) % KFC;
    int l = idx / (256*KFC);
    int i = kk / 9, s = kk % 9;
    float v = (s==0) ? bw[(l*256 + o)*256 + i]
                     : sw[((l*256 + o)*256 + i)*8 + (s-1)];
    d_wfcgT[idx] = v;
}
__global__ void prep_fin(const float* __restrict__ bw, const float* __restrict__ sw){
    int idx = blockIdx.x*blockDim.x + threadIdx.x;
    if (idx >= 2*KFC) return;
    int kk = idx % KFC;
    int l = idx / KFC;
    int i = kk / 9, s = kk % 9;
    float v = (s==0) ? bw[l*256 + i] : sw[(l*256 + i)*8 + (s-1)];
    d_wfinT[idx] = v;
}

// ---------------- input linear (both branches in one launch) ----------------
__global__ void __launch_bounds__(256) input_linear2(
        const float* __restrict__ xf, const float* __restrict__ af,
        const float* __restrict__ w0, const float* __restrict__ b0,
        const float* __restrict__ w1, const float* __restrict__ b1){
    extern __shared__ float sm[];
    float* As = sm;              // [64][96]
    float* Ws = sm + 64*96;      // [96][WSP]
    int br = blockIdx.y;
    const float* feat = br ? af : xf;
    const float* w    = br ? w1 : w0;
    const float* bias = br ? b1 : b0;
    int IN = br ? 43 : 93;
    int tid = threadIdx.x;
    int nbase = blockIdx.x * 64;
    for (int idx = tid; idx < 64*IN; idx += 256){
        int n = idx / IN, i = idx % IN;
        As[n*96 + i] = feat[(size_t)(nbase+n)*IN + i];
    }
    for (int idx = tid; idx < NF*IN; idx += 256){
        int o = idx / IN, i = idx % IN;
        Ws[i*WSP + o] = w[idx];
    }
    __syncthreads();
    int ng = (tid >> 5) * 8;
    int og = (tid & 31) * 4;
    unsigned long long acc[4][4];
#pragma unroll
    for (int p = 0; p < 4; p++)
#pragma unroll
        for (int c = 0; c < 4; c++) acc[p][c] = 0ull;
    for (int k = 0; k < IN; k++){
        float4 w4 = *(float4*)&Ws[k*WSP + og];
        unsigned long long q0 = pk2(w4.x, w4.x), q1 = pk2(w4.y, w4.y);
        unsigned long long q2 = pk2(w4.z, w4.z), q3 = pk2(w4.w, w4.w);
#pragma unroll
        for (int p = 0; p < 4; p++){
            unsigned long long a = pk2(As[(ng+2*p)*96 + k], As[(ng+2*p+1)*96 + k]);
            ffma2(acc[p][0], a, q0); ffma2(acc[p][1], a, q1);
            ffma2(acc[p][2], a, q2); ffma2(acc[p][3], a, q3);
        }
    }
    float4 b4 = *(float4*)&bias[og];
    float* xout = d_xbuf[br];
#pragma unroll
    for (int p = 0; p < 4; p++){
        float lo[4], hi[4];
#pragma unroll
        for (int c = 0; c < 4; c++) upk2(acc[p][c], lo[c], hi[c]);
        float4 v0; v0.x = lo[0]+b4.x; v0.y = lo[1]+b4.y; v0.z = lo[2]+b4.z; v0.w = lo[3]+b4.w;
        float4 v1; v1.x = hi[0]+b4.x; v1.y = hi[1]+b4.y; v1.z = hi[2]+b4.z; v1.w = hi[3]+b4.w;
        *(float4*)&xout[(size_t)(nbase+ng+2*p  )*NF + og] = v0;
        *(float4*)&xout[(size_t)(nbase+ng+2*p+1)*NF + og] = v1;
    }
}

// ---------------- GIN aggregation, both branches (per-graph CTA) ----------------
__global__ void __launch_bounds__(256) aggregate2(int n, int lev,
        const int* __restrict__ ei0, const int* __restrict__ ei1){
    extern __shared__ float xs[];
    __shared__ int cnt[256];
    __shared__ int wo[256];
    __shared__ int scan[256];
    __shared__ int rowptr[257];
    __shared__ int csr[EPG];
    int b = blockIdx.x >> 7, g = blockIdx.x & 127;
    int tid = threadIdx.x;
    const int* esrc; const int* edst; int m; int ebase;
    if (lev == 0){
        const int* ei = b ? ei1 : ei0;
        esrc = ei; edst = ei + NE; m = EPG; ebase = g*EPG;
    } else if (lev == 1){
        esrc = d_srcA[b]; edst = d_dstA[b]; m = d_ecntA[b*G+g]; ebase = g*EPG2;
    } else {
        esrc = d_srcB[b]; edst = d_dstB[b]; m = d_ecntB[b*G+g]; ebase = g*EPG2;
    }
    float4* xs4 = (float4*)xs;
    const float4* xin4 = (const float4*)d_xbuf[b];
    for (int idx = tid; idx < n*32; idx += 256)
        xs4[idx] = xin4[(size_t)g*n*32 + idx];
    cnt[tid] = 0; wo[tid] = 0;
    __syncthreads();
    int nodebase = g*n;
    for (int e = tid; e < m; e += 256)
        atomicAdd(&cnt[edst[ebase+e] - nodebase], 1);
    __syncthreads();
    scan[tid] = cnt[tid];
    __syncthreads();
#pragma unroll
    for (int off = 1; off < 256; off <<= 1){
        int v = (tid >= off) ? scan[tid-off] : 0;
        __syncthreads();
        scan[tid] += v;
        __syncthreads();
    }
    rowptr[tid+1] = scan[tid];
    if (tid == 0) rowptr[0] = 0;
    __syncthreads();
    for (int e = tid; e < m; e += 256){
        int d = edst[ebase+e] - nodebase;
        int pos = rowptr[d] + atomicAdd(&wo[d], 1);
        csr[pos] = esrc[ebase+e] - nodebase;
    }
    __syncthreads();
    int wid = tid >> 5, lane = tid & 31;
    float4* agg4 = (float4*)d_agg[b];
    for (int i = wid; i < n; i += 8){
        float4 acc = xs4[i*32 + lane];
        int p1 = rowptr[i+1];
        for (int p = rowptr[i]; p < p1; p++){
            float4 v = xs4[csr[p]*32 + lane];
            acc.x += v.x; acc.y += v.y; acc.z += v.z; acc.w += v.w;
        }
        agg4[(size_t)(nodebase + i)*32 + lane] = acc;
    }
}

// ---------------- bf16 HMMA KAN conv GEMM + relu, both branches, IN PLACE ----------------
__global__ void __launch_bounds__(256, 2) kan_gemm_mma2(int cpb, int lev){
    extern __shared__ char smraw[];
    unsigned short* AHs = (unsigned short*)(smraw + SM_AH);  // [128][80] bf16
    unsigned short* ALs = (unsigned short*)(smraw + SM_AL);
    unsigned* BH = (unsigned*)(smraw + SM_BH);               // [5][16][64] u32
    unsigned* BL = (unsigned*)(smraw + SM_BL);
    int br = blockIdx.x / cpb;
    int cid = blockIdx.x % cpb;
    int level = br*3 + lev;
    float* agg = d_agg[br];
    int tid = threadIdx.x;
    int w = tid >> 5, lane = tid & 31;
    int gid = lane >> 2, tig = lane & 3;
    int nb = cid * TN;
    int M0 = (w & 3) * 32;
    int NT0 = (w >> 2) * 8;

    float cacc[2][8][4];
#pragma unroll
    for (int mf = 0; mf < 2; mf++)
#pragma unroll
        for (int nf = 0; nf < 8; nf++)
#pragma unroll
            for (int q = 0; q < 4; q++) cacc[mf][nf][q] = 0.f;

    for (int c = 0; c < NCH; c++){
        for (int t = tid; t < TN*8; t += 256){
            int nn = t >> 3, ii = t & 7;
            float xv = agg[(size_t)(nb+nn)*NF + c*8 + ii];
            float bs[8]; bsplines8(xv, bs);
            float v[9];
            v[0] = xv;
#pragma unroll
            for (int s = 0; s < 8; s++) v[1+s] = bs[s];
            unsigned short* dh = &AHs[nn*80 + ii*9];
            unsigned short* dl = &ALs[nn*80 + ii*9];
#pragma unroll
            for (int q = 0; q < 9; q++){
                __nv_bfloat16 h = __float2bfloat16(v[q]);
                dh[q] = __bfloat16_as_ushort(h);
                dl[q] = __bfloat16_as_ushort(__float2bfloat16(v[q] - __bfloat162float(h)));
            }
        }
        if (tid < 128){
            uint4 z = {0,0,0,0};
            *(uint4*)(smraw + SM_AH + tid*ROWB + 144) = z;
            *(uint4*)(smraw + SM_AL + tid*ROWB + 144) = z;
        }
        {
            const float4* sh = (const float4*)(d_wcb + ((size_t)(level*2+0)*NCH + c)*5120);
            const float4* sl = (const float4*)(d_wcb + ((size_t)(level*2+1)*NCH + c)*5120);
            float4* bh4 = (float4*)BH;
            float4* bl4 = (float4*)BL;
            for (int i = tid; i < 1280; i += 256){
                bh4[i] = sh[i];
                bl4[i] = sl[i];
            }
        }
        __syncthreads();
#pragma unroll
        for (int ks = 0; ks < 5; ks++){
            unsigned aH[2][4], aL[2][4];
#pragma unroll
            for (int mf = 0; mf < 2; mf++){
                int r0 = M0 + mf*16 + gid;
                int bo = ks*32 + tig*4;
                aH[mf][0] = *(const unsigned*)(smraw + SM_AH + r0*ROWB + bo);
                aH[mf][1] = *(const unsigned*)(smraw + SM_AH + (r0+8)*ROWB + bo);
                aH[mf][2] = *(const unsigned*)(smraw + SM_AH + r0*ROWB + bo + 16);
                aH[mf][3] = *(const unsigned*)(smraw + SM_AH + (r0+8)*ROWB + bo + 16);
                aL[mf][0] = *(const unsigned*)(smraw + SM_AL + r0*ROWB + bo);
                aL[mf][1] = *(const unsigned*)(smraw + SM_AL + (r0+8)*ROWB + bo);
                aL[mf][2] = *(const unsigned*)(smraw + SM_AL + r0*ROWB + bo + 16);
                aL[mf][3] = *(const unsigned*)(smraw + SM_AL + (r0+8)*ROWB + bo + 16);
            }
#pragma unroll
            for (int nf = 0; nf < 8; nf++){
                int bi = (ks*16 + NT0 + nf)*64 + lane*2;
                unsigned bh0 = BH[bi], bh1 = BH[bi+1];
                unsigned bl0 = BL[bi], bl1 = BL[bi+1];
#pragma unroll
                for (int mf = 0; mf < 2; mf++){
                    mma16816(cacc[mf][nf], aH[mf], bh0, bh1);
                    mma16816(cacc[mf][nf], aH[mf], bl0, bl1);
                    mma16816(cacc[mf][nf], aL[mf], bh0, bh1);
                }
            }
        }
        __syncthreads();
    }
#pragma unroll
    for (int mf = 0; mf < 2; mf++){
#pragma unroll
        for (int nf = 0; nf < 8; nf++){
            int row0 = nb + M0 + mf*16 + gid;
            int col = NT0*8 + nf*8 + tig*2;
            float2 v0; v0.x = fmaxf(cacc[mf][nf][0], 0.f); v0.y = fmaxf(cacc[mf][nf][1], 0.f);
            float2 v1; v1.x = fmaxf(cacc[mf][nf][2], 0.f); v1.y = fmaxf(cacc[mf][nf][3], 0.f);
            *(float2*)&agg[(size_t)row0*NF + col] = v0;
            *(float2*)&agg[(size_t)(row0+8)*NF + col] = v1;
        }
    }
}

// ---------------- fused pool + edge-compact + readout, both branches ----------------
__global__ void __launch_bounds__(256) pool_fused2(int n, int k, int lev,
        const float* __restrict__ pool_p,
        const int* __restrict__ ei0, const int* __restrict__ ei1){
    __shared__ float s[256];
    __shared__ int pos[256];
    __shared__ unsigned char kf[256];
    __shared__ int maxv[128];
    __shared__ float sumv[128];
    __shared__ int ecnt_s;
    int b = blockIdx.x >> 7, g = blockIdx.x & 127;
    int tid = threadIdx.x;
    int wid = tid >> 5, lane = tid & 31;
    int nodebase = g*n;
    const float* p = pool_p + (b*3 + lev)*NF;
    const float* agg = d_agg[b];
    const int* esrcIn; const int* edstIn; int m; int ebIn;
    if (lev == 0){
        const int* ei = b ? ei1 : ei0;
        esrcIn = ei; edstIn = ei + NE; m = EPG; ebIn = g*EPG;
    } else if (lev == 1){
        esrcIn = d_srcA[b]; edstIn = d_dstA[b]; m = d_ecntA[b*G+g]; ebIn = g*EPG2;
    } else {
        esrcIn = d_srcB[b]; edstIn = d_dstB[b]; m = d_ecntB[b*G+g]; ebIn = g*EPG2;
    }
    for (int i = wid; i < n; i += 8){
        float v = 0.f;
#pragma unroll
        for (int t = 0; t < 4; t++){
            int f = lane + t*32;
            v += agg[(size_t)(nodebase+i)*NF + f] * p[f];
        }
#pragma unroll
        for (int o = 16; o > 0; o >>= 1) v += __shfl_down_sync(0xffffffffu, v, o);
        if (lane == 0) s[i] = 1.0f/(1.0f + expf(-v));
    }
    if (tid < 128){ maxv[tid] = 0; sumv[tid] = 0.f; }
    if (tid == 0) ecnt_s = 0;
    __syncthreads();
    for (int i = tid; i < n; i += 256){
        float si = s[i]; int c = 0;
        for (int j = 0; j < n; j++){
            float sj = s[j];
            c += (sj > si) || (sj == si && j < i);
        }
        kf[i] = (c < k) ? 1 : 0;
    }
    __syncthreads();
    for (int i = tid; i < n; i += 256){
        int c = 0;
        for (int j = 0; j < i; j++) c += kf[j];
        pos[i] = c;
    }
    __syncthreads();
    float* xout = d_xbuf[b];
    for (int t = tid; t < n*NF; t += 256){
        int i = t >> 7, f = t & 127;
        if (kf[i]){
            float v = agg[(size_t)(nodebase+i)*NF + f] * s[i];
            xout[(size_t)(g*k + pos[i])*NF + f] = v;
            atomicMax(&maxv[f], __float_as_int(v));
            atomicAdd(&sumv[f], v);
        }
    }
    if (lev < 2){
        int ebOut = g*EPG2;
        int* esrcOut = (lev == 0) ? d_srcA[b] : d_srcB[b];
        int* edstOut = (lev == 0) ? d_dstA[b] : d_dstB[b];
        for (int e = tid; e < m; e += 256){
            int sN = esrcIn[ebIn+e] - nodebase;
            int dN = edstIn[ebIn+e] - nodebase;
            if (kf[sN] && kf[dN]){
                int slot = atomicAdd(&ecnt_s, 1);
                esrcOut[ebOut+slot] = g*k + pos[sN];
                edstOut[ebOut+slot] = g*k + pos[dN];
            }
        }
    }
    __syncthreads();
    if (tid < 128){
        float* o = &d_read[((size_t)(b*3+lev)*G + g)*256];
        o[tid] = __int_as_float(maxv[tid]);
        o[128 + tid] = sumv[tid] / (float)k;
    }
    if (tid == 0 && lev < 2){
        if (lev == 0) d_ecntA[b*G+g] = ecnt_s; else d_ecntB[b*G+g] = ecnt_s;
    }
}

// ---------------- head: combine readouts + fc_g KAN (256->256) ----------------
__global__ void __launch_bounds__(256) head_fcg(int b, const float* __restrict__ wr,
                                                float* __restrict__ out){
    extern __shared__ float sm[];
    float* X  = sm;                 // [16][256]
    float* Et = sm + 16*256;        // [72][16]
    float* Ws = Et + 72*16;         // [72][128]
    int tid = threadIdx.x;
    int rb = blockIdx.x * 16;
    int ob = blockIdx.y * 128;
    float w0 = wr[0], w1 = wr[1], w2 = wr[2];
    for (int idx = tid; idx < 16*256; idx += 256){
        int r = idx >> 8, i = idx & 255;
        int row = rb + r;
        float v;
        if (b == 0){
            float a0 = d_read[((size_t)0*G + row)*256 + i];
            float a1 = d_read[((size_t)1*G + row)*256 + i];
            v = fmaxf(a0, 0.f) + fmaxf(a1, 0.f);
        } else {
            float a0 = d_read[((size_t)3*G + row)*256 + i];
            float a1 = d_read[((size_t)4*G + row)*256 + i];
            float a2 = d_read[((size_t)5*G + row)*256 + i];
            v = w0*fmaxf(a0, 0.f) + w1*fmaxf(a1, 0.f) + w2*fmaxf(a2, 0.f);
        }
        X[idx] = v;
    }
    const float* __restrict__ W = d_wfcgT + (size_t)b*KFC*256;
    int rg = (tid >> 5) * 2;
    int og = (tid & 31) * 4;
    unsigned long long acc[4];
#pragma unroll
    for (int c = 0; c < 4; c++) acc[c] = 0ull;

    for (int c = 0; c < 32; c++){
        int i0 = c*8;
        __syncthreads();
        if (tid < 128){
            int r = tid >> 3, ii = tid & 7;
            float xv = X[r*256 + i0 + ii];
            float bs[8]; bsplines8(xv, bs);
            Et[(ii*9)*16 + r] = xv;
#pragma unroll
            for (int s = 0; s < 8; s++) Et[(ii*9+1+s)*16 + r] = bs[s];
        }
        for (int idx = tid; idx < 72*128; idx += 256){
            int kk = idx >> 7, j = idx & 127;
            Ws[idx] = W[((size_t)c*72 + kk)*256 + ob + j];
        }
        __syncthreads();
#pragma unroll 4
        for (int kk = 0; kk < 72; kk++){
            unsigned long long a = *(const unsigned long long*)&Et[kk*16 + rg];
            float4 w4 = *(const float4*)&Ws[kk*128 + og];
            ffma2(acc[0], a, pk2(w4.x, w4.x));
            ffma2(acc[1], a, pk2(w4.y, w4.y));
            ffma2(acc[2], a, pk2(w4.z, w4.z));
            ffma2(acc[3], a, pk2(w4.w, w4.w));
        }
    }
    int outbase = 128 + b*(G*256);
    float lo[4], hi[4];
#pragma unroll
    for (int c = 0; c < 4; c++) upk2(acc[c], lo[c], hi[c]);
    int row0 = rb + rg, row1 = rb + rg + 1;
    float4 v0; v0.x = lo[0]; v0.y = lo[1]; v0.z = lo[2]; v0.w = lo[3];
    float4 v1; v1.x = hi[0]; v1.y = hi[1]; v1.z = hi[2]; v1.w = hi[3];
    *(float4*)&d_xg[((size_t)b*G + row0)*256 + ob + og] = v0;
    *(float4*)&d_xg[((size_t)b*G + row1)*256 + ob + og] = v1;
    *(float4*)&out[outbase + (size_t)row0*256 + ob + og] = v0;
    *(float4*)&out[outbase + (size_t)row1*256 + ob + og] = v1;
}

// ---------------- head: fc_final KAN (256->1) ----------------
__global__ void __launch_bounds__(256) head_fin(int b, float* __restrict__ out){
    __shared__ float Xs[256];
    __shared__ float red[256];
    int row = blockIdx.x, tid = threadIdx.x;
    Xs[tid] = d_xg[((size_t)b*G + row)*256 + tid];
    __syncthreads();
    float xv = Xs[tid];
    float bs[8]; bsplines8(xv, bs);
    const float* W = d_wfinT + (size_t)b*KFC + tid*9;
    float acc = xv * W[0];
#pragma unroll
    for (int s = 0; s < 8; s++) acc += bs[s]*W[1+s];
    red[tid] = acc;
    __syncthreads();
    for (int o = 128; o > 0; o >>= 1){
        if (tid < o) red[tid] += red[tid+o];
        __syncthreads();
    }
    if (tid == 0){
        int base = (b == 0) ? 0 : (128 + 2*G*256);
        out[base + row] = red[0];
    }
}

// ---------------- launch ----------------
extern "C" void kernel_launch(void* const* d_in, const int* in_sizes, int n_in,
                              void* d_out, int out_size){
    (void)in_sizes; (void)n_in; (void)out_size;
    const float* x       = (const float*)d_in[0];
    const float* a       = (const float*)d_in[1];
    const float* dt0_w   = (const float*)d_in[2];
    const float* dt0_b   = (const float*)d_in[3];
    const float* dt1_w   = (const float*)d_in[4];
    const float* dt1_b   = (const float*)d_in[5];
    const float* conv_bw = (const float*)d_in[6];
    const float* conv_sw = (const float*)d_in[7];
    const float* fcg_bw  = (const float*)d_in[8];
    const float* fcg_sw  = (const float*)d_in[9];
    const float* fin_bw  = (const float*)d_in[10];
    const float* fin_sw  = (const float*)d_in[11];
    const float* pool_p  = (const float*)d_in[12];
    const float* w_r     = (const float*)d_in[13];
    const int* edge_index = (const int*)d_in[14];
    const int* edge       = (const int*)d_in[15];
    float* out = (float*)d_out;

    cudaFuncSetAttribute(aggregate2,    cudaFuncAttributeMaxDynamicSharedMemorySize, 256*128*4);
    cudaFuncSetAttribute(kan_gemm_mma2, cudaFuncAttributeMaxDynamicSharedMemorySize, SM_TOT);
    cudaFuncSetAttribute(input_linear2, cudaFuncAttributeMaxDynamicSharedMemorySize, (64*96+96*WSP)*4);
    cudaFuncSetAttribute(head_fcg,      cudaFuncAttributeMaxDynamicSharedMemorySize, (16*256+72*16+72*128)*4);

    // launch order keeps kan_gemm_mma2 L0 at slot #4 for the profiler.
    prep_w_mma<<<(6*2*16*5*16*64+255)/256, 256>>>(conv_bw, conv_sw);
    input_linear2<<<dim3(NNODE/64, 2), 256, (64*96+96*WSP)*4>>>(x, a, dt0_w, dt0_b, dt1_w, dt1_b);

    int n = 256;
    for (int lev = 0; lev < 3; lev++){
        int k = n/2;
        int cpb = G*n/TN;
        aggregate2<<<2*G, 256, n*128*4>>>(n, lev, edge_index, edge);
        kan_gemm_mma2<<<2*cpb, 256, SM_TOT>>>(cpb, lev);
        pool_fused2<<<2*G, 256>>>(n, k, lev, pool_p, edge_index, edge);
        n = k;
    }
    prep_fcg<<<(2*KFC*256+255)/256, 256>>>(fcg_bw, fcg_sw);
    prep_fin<<<(2*KFC+255)/256, 256>>>(fin_bw, fin_sw);
    for (int b = 0; b < 2; b++){
        head_fcg<<<dim3(8,2), 256, (16*256+72*16+72*128)*4>>>(b, w_r, out);
        head_fin<<<G, 256>>>(b, out);
    }
}

// round 17
// speedup vs baseline: 1.8642x; 1.1110x over previous
#include <cuda_runtime.h>
#include <cuda_bf16.h>
#include <math.h>

#define G 128
#define NPG0 256
#define NNODE (G*NPG0)      // 32768
#define NF 128
#define EPG 4096
#define EPG2 (EPG/2)        // per-graph compacted edge capacity
#define NE (G*EPG)          // 524288
#define NE2 (G*EPG2)
#define KFC (256*9)         // 2304
#define WSP 132             // padded Ws stride in input_linear
#define TN 128              // nodes per kan CTA tile (M)
#define NCH 16              // K chunks: 8 inputs x 10 slots (9 real + 1 pad) = 80
#define ROWB 160            // bytes per A smem row (80 bf16)
// smem byte offsets for kan_gemm_mma
#define SM_AH 0
#define SM_AL 20480
#define SM_BH 40960
#define SM_BL 61440
#define SM_TOT 81920

// ---------------- scratch (device globals; no allocation) ----------------
// INVARIANT: referenced from DEVICE code only (host shadow-symbol UB lesson).
__device__ float d_xbuf[2][NNODE*NF];       // 32 MiB
__device__ float d_agg [2][NNODE*NF];       // 32 MiB (gemm in place)
__device__ int   d_srcA[2][NE2];
__device__ int   d_dstA[2][NE2];
__device__ int   d_srcB[2][NE2];
__device__ int   d_dstB[2][NE2];
__device__ int   d_ecntA[2*G];
__device__ int   d_ecntB[2*G];
__device__ float d_read[2*3*G*256];
// B fragments: [6][2 terms][16 chunks][5 ksteps][16 ntiles][32 lanes][2 regs] u32
__device__ unsigned d_wcb[6*2*16*5*16*64];  // 3.75 MiB
__device__ float d_wfcgT[2*KFC*256];        // 4.5 MiB
__device__ float d_wfinT[2*KFC];
__device__ float d_xg[2*G*256];

// ---------------- packed f32x2 helpers ----------------
__device__ __forceinline__ unsigned long long pk2(float lo, float hi){
    unsigned long long r;
    asm("mov.b64 %0, {%1, %2};" : "=l"(r) : "f"(lo), "f"(hi));
    return r;
}
__device__ __forceinline__ void upk2(unsigned long long v, float& lo, float& hi){
    asm("mov.b64 {%0, %1}, %2;" : "=f"(lo), "=f"(hi) : "l"(v));
}
__device__ __forceinline__ void ffma2(unsigned long long& acc, unsigned long long a,
                                      unsigned long long b){
    asm("fma.rn.f32x2 %0, %1, %2, %0;" : "+l"(acc) : "l"(a), "l"(b));
}

// bf16x2 pack: hi half = a1, lo half = a0
__device__ __forceinline__ unsigned cvt2bf(float a1, float a0){
    unsigned r;
    asm("cvt.rn.bf16x2.f32 %0, %1, %2;" : "=r"(r) : "f"(a1), "f"(a0));
    return r;
}

// ---------------- bf16 mma.sync m16n8k16 (base PTX) ----------------
__device__ __forceinline__ void mma16816(float* c, const unsigned* a,
                                         unsigned b0, unsigned b1){
    asm volatile("mma.sync.aligned.m16n8k16.row.col.f32.bf16.bf16.f32 "
        "{%0,%1,%2,%3}, {%4,%5,%6,%7}, {%8,%9}, {%0,%1,%2,%3};"
        : "+f"(c[0]), "+f"(c[1]), "+f"(c[2]), "+f"(c[3])
        : "r"(a[0]), "r"(a[1]), "r"(a[2]), "r"(a[3]), "r"(b0), "r"(b1));
}

// ---------------- B-spline basis (cubic, GRID=5, 8 outputs) ----------------
__device__ __forceinline__ float knot(int j){ return (float)(j-3)*0.4f - 1.0f; }

__device__ __forceinline__ void bsplines8(float x, float* out){
    float b[11];
#pragma unroll
    for (int j = 0; j < 11; j++){
        float g0 = knot(j), g1 = knot(j+1);
        b[j] = (x >= g0 && x < g1) ? 1.0f : 0.0f;
    }
#pragma unroll
    for (int k = 1; k <= 3; k++){
#pragma unroll
        for (int j = 0; j <= 10-k; j++){
            float gj  = knot(j),     gjk  = knot(j+k);
            float gj1 = knot(j+1),   gjk1 = knot(j+k+1);
            b[j] = (x - gj)*(1.0f/(gjk - gj))*b[j]
                 + (gjk1 - x)*(1.0f/(gjk1 - gj1))*b[j+1];
        }
    }
#pragma unroll
    for (int j = 0; j < 8; j++) out[j] = b[j];
}

// ---------------- weight prep: pack conv weights into mma B-fragment layout ----------------
// 10-slot-per-input padded K layout: slot = i_local*10 + s, s<9 real, s==9 zero.
__global__ void prep_w_mma(const float* __restrict__ bw, const float* __restrict__ sw){
    int idx = blockIdx.x*blockDim.x + threadIdx.x;
    if (idx >= 6*2*16*5*16*64) return;
    int r    = idx & 1;
    int lane = (idx >> 1) & 31;
    int nt   = (idx >> 6) & 15;
    int ks   = (idx >> 10) % 5;
    int c    = (idx / 5120) & 15;
    int t    = (idx / 81920) % 2;
    int l    = idx / 163840;
    int n = nt*8 + (lane >> 2);
    int slot0 = ks*16 + (lane & 3)*2 + r*8;
    unsigned out = 0;
#pragma unroll
    for (int e = 0; e < 2; e++){
        int slot = slot0 + e;                 // [0,80)
        int i = c*8 + slot/10;
        int s = slot % 10;
        float v = 0.f;
        if (s == 0) v = bw[(l*NF + n)*NF + i];
        else if (s <= 8) v = sw[((l*NF + n)*NF + i)*8 + (s-1)];
        __nv_bfloat16 vh = __float2bfloat16(v);
        unsigned short bits;
        if (t == 0) bits = __bfloat16_as_ushort(vh);
        else        bits = __bfloat16_as_ushort(__float2bfloat16(v - __bfloat162float(vh)));
        out |= ((unsigned)bits) << (16*e);
    }
    d_wcb[idx] = out;
}
__global__ void prep_fcg(const float* __restrict__ bw, const float* __restrict__ sw){
    int idx = blockIdx.x*blockDim.x + threadIdx.x;
    if (idx >= 2*KFC*256) return;
    int o = idx % 256;
    int kk = (idx / 256) % KFC;
    int l = idx / (256*KFC);
    int i = kk / 9, s = kk % 9;
    float v = (s==0) ? bw[(l*256 + o)*256 + i]
                     : sw[((l*256 + o)*256 + i)*8 + (s-1)];
    d_wfcgT[idx] = v;
}
__global__ void prep_fin(const float* __restrict__ bw, const float* __restrict__ sw){
    int idx = blockIdx.x*blockDim.x + threadIdx.x;
    if (idx >= 2*KFC) return;
    int kk = idx % KFC;
    int l = idx / KFC;
    int i = kk / 9, s = kk % 9;
    float v = (s==0) ? bw[l*256 + i] : sw[(l*256 + i)*8 + (s-1)];
    d_wfinT[idx] = v;
}

// ---------------- input linear (both branches in one launch) ----------------
__global__ void __launch_bounds__(256) input_linear2(
        const float* __restrict__ xf, const float* __restrict__ af,
        const float* __restrict__ w0, const float* __restrict__ b0,
        const float* __restrict__ w1, const float* __restrict__ b1){
    extern __shared__ float sm[];
    float* As = sm;              // [64][96]
    float* Ws = sm + 64*96;      // [96][WSP]
    int br = blockIdx.y;
    const float* feat = br ? af : xf;
    const float* w    = br ? w1 : w0;
    const float* bias = br ? b1 : b0;
    int IN = br ? 43 : 93;
    int tid = threadIdx.x;
    int nbase = blockIdx.x * 64;
    for (int idx = tid; idx < 64*IN; idx += 256){
        int n = idx / IN, i = idx % IN;
        As[n*96 + i] = feat[(size_t)(nbase+n)*IN + i];
    }
    for (int idx = tid; idx < NF*IN; idx += 256){
        int o = idx / IN, i = idx % IN;
        Ws[i*WSP + o] = w[idx];
    }
    __syncthreads();
    int ng = (tid >> 5) * 8;
    int og = (tid & 31) * 4;
    unsigned long long acc[4][4];
#pragma unroll
    for (int p = 0; p < 4; p++)
#pragma unroll
        for (int c = 0; c < 4; c++) acc[p][c] = 0ull;
    for (int k = 0; k < IN; k++){
        float4 w4 = *(float4*)&Ws[k*WSP + og];
        unsigned long long q0 = pk2(w4.x, w4.x), q1 = pk2(w4.y, w4.y);
        unsigned long long q2 = pk2(w4.z, w4.z), q3 = pk2(w4.w, w4.w);
#pragma unroll
        for (int p = 0; p < 4; p++){
            unsigned long long a = pk2(As[(ng+2*p)*96 + k], As[(ng+2*p+1)*96 + k]);
            ffma2(acc[p][0], a, q0); ffma2(acc[p][1], a, q1);
            ffma2(acc[p][2], a, q2); ffma2(acc[p][3], a, q3);
        }
    }
    float4 b4 = *(float4*)&bias[og];
    float* xout = d_xbuf[br];
#pragma unroll
    for (int p = 0; p < 4; p++){
        float lo[4], hi[4];
#pragma unroll
        for (int c = 0; c < 4; c++) upk2(acc[p][c], lo[c], hi[c]);
        float4 v0; v0.x = lo[0]+b4.x; v0.y = lo[1]+b4.y; v0.z = lo[2]+b4.z; v0.w = lo[3]+b4.w;
        float4 v1; v1.x = hi[0]+b4.x; v1.y = hi[1]+b4.y; v1.z = hi[2]+b4.z; v1.w = hi[3]+b4.w;
        *(float4*)&xout[(size_t)(nbase+ng+2*p  )*NF + og] = v0;
        *(float4*)&xout[(size_t)(nbase+ng+2*p+1)*NF + og] = v1;
    }
}

// ---------------- GIN aggregation, both branches (per-graph CTA) ----------------
__global__ void __launch_bounds__(256) aggregate2(int n, int lev,
        const int* __restrict__ ei0, const int* __restrict__ ei1){
    extern __shared__ float xs[];
    __shared__ int cnt[256];
    __shared__ int wo[256];
    __shared__ int scan[256];
    __shared__ int rowptr[257];
    __shared__ int csr[EPG];
    int b = blockIdx.x >> 7, g = blockIdx.x & 127;
    int tid = threadIdx.x;
    const int* esrc; const int* edst; int m; int ebase;
    if (lev == 0){
        const int* ei = b ? ei1 : ei0;
        esrc = ei; edst = ei + NE; m = EPG; ebase = g*EPG;
    } else if (lev == 1){
        esrc = d_srcA[b]; edst = d_dstA[b]; m = d_ecntA[b*G+g]; ebase = g*EPG2;
    } else {
        esrc = d_srcB[b]; edst = d_dstB[b]; m = d_ecntB[b*G+g]; ebase = g*EPG2;
    }
    float4* xs4 = (float4*)xs;
    const float4* xin4 = (const float4*)d_xbuf[b];
    for (int idx = tid; idx < n*32; idx += 256)
        xs4[idx] = xin4[(size_t)g*n*32 + idx];
    cnt[tid] = 0; wo[tid] = 0;
    __syncthreads();
    int nodebase = g*n;
    for (int e = tid; e < m; e += 256)
        atomicAdd(&cnt[edst[ebase+e] - nodebase], 1);
    __syncthreads();
    scan[tid] = cnt[tid];
    __syncthreads();
#pragma unroll
    for (int off = 1; off < 256; off <<= 1){
        int v = (tid >= off) ? scan[tid-off] : 0;
        __syncthreads();
        scan[tid] += v;
        __syncthreads();
    }
    rowptr[tid+1] = scan[tid];
    if (tid == 0) rowptr[0] = 0;
    __syncthreads();
    for (int e = tid; e < m; e += 256){
        int d = edst[ebase+e] - nodebase;
        int pos = rowptr[d] + atomicAdd(&wo[d], 1);
        csr[pos] = esrc[ebase+e] - nodebase;
    }
    __syncthreads();
    int wid = tid >> 5, lane = tid & 31;
    float4* agg4 = (float4*)d_agg[b];
    for (int i = wid; i < n; i += 8){
        float4 acc = xs4[i*32 + lane];
        int p1 = rowptr[i+1];
        for (int p = rowptr[i]; p < p1; p++){
            float4 v = xs4[csr[p]*32 + lane];
            acc.x += v.x; acc.y += v.y; acc.z += v.z; acc.w += v.w;
        }
        agg4[(size_t)(nodebase + i)*32 + lane] = acc;
    }
}

// ---------------- bf16 HMMA KAN conv GEMM + relu, both branches, IN PLACE ----------------
__global__ void __launch_bounds__(256, 2) kan_gemm_mma2(int cpb, int lev){
    extern __shared__ char smraw[];
    unsigned* AH32 = (unsigned*)(smraw + SM_AH);   // [128][40] u32 (80 bf16/row)
    unsigned* AL32 = (unsigned*)(smraw + SM_AL);
    unsigned* BH = (unsigned*)(smraw + SM_BH);     // [5][16][64] u32
    unsigned* BL = (unsigned*)(smraw + SM_BL);
    int br = blockIdx.x / cpb;
    int cid = blockIdx.x % cpb;
    int level = br*3 + lev;
    float* agg = d_agg[br];
    int tid = threadIdx.x;
    int w = tid >> 5, lane = tid & 31;
    int gid = lane >> 2, tig = lane & 3;
    int nb = cid * TN;
    int M0 = (w & 3) * 32;
    int NT0 = (w >> 2) * 8;

    float cacc[2][8][4];
#pragma unroll
    for (int mf = 0; mf < 2; mf++)
#pragma unroll
        for (int nf = 0; nf < 8; nf++)
#pragma unroll
            for (int q = 0; q < 4; q++) cacc[mf][nf][q] = 0.f;

    for (int c = 0; c < NCH; c++){
        // ---- expansion: 128 nodes x 8 inputs -> 10-slot padded hi/lo, packed cvts ----
        for (int t = tid; t < TN*8; t += 256){
            int nn = t >> 3, ii = t & 7;
            float xv = agg[(size_t)(nb+nn)*NF + c*8 + ii];
            float bs[8]; bsplines8(xv, bs);
            float v[10];
            v[0] = xv;
#pragma unroll
            for (int s = 0; s < 8; s++) v[1+s] = bs[s];
            v[9] = 0.f;
            unsigned* dh = &AH32[nn*40 + ii*5];
            unsigned* dl = &AL32[nn*40 + ii*5];
#pragma unroll
            for (int q = 0; q < 5; q++){
                float a0 = v[2*q], a1 = v[2*q+1];
                unsigned h = cvt2bf(a1, a0);
                float f0 = __uint_as_float(h << 16);
                float f1 = __uint_as_float(h & 0xFFFF0000u);
                dh[q] = h;
                dl[q] = cvt2bf(a1 - f1, a0 - f0);
            }
        }
        // ---- B chunk copy (pre-swizzled fragment layout) ----
        {
            const float4* sh = (const float4*)(d_wcb + ((size_t)(level*2+0)*NCH + c)*5120);
            const float4* sl = (const float4*)(d_wcb + ((size_t)(level*2+1)*NCH + c)*5120);
            float4* bh4 = (float4*)BH;
            float4* bl4 = (float4*)BL;
            for (int i = tid; i < 1280; i += 256){
                bh4[i] = sh[i];
                bl4[i] = sl[i];
            }
        }
        __syncthreads();
        // ---- MMA: 5 ksteps x (2 mfrags x 8 ntiles x 3 terms) ----
#pragma unroll
        for (int ks = 0; ks < 5; ks++){
            unsigned aH[2][4], aL[2][4];
#pragma unroll
            for (int mf = 0; mf < 2; mf++){
                int r0 = M0 + mf*16 + gid;
                int bo = ks*32 + tig*4;
                aH[mf][0] = *(const unsigned*)(smraw + SM_AH + r0*ROWB + bo);
                aH[mf][1] = *(const unsigned*)(smraw + SM_AH + (r0+8)*ROWB + bo);
                aH[mf][2] = *(const unsigned*)(smraw + SM_AH + r0*ROWB + bo + 16);
                aH[mf][3] = *(const unsigned*)(smraw + SM_AH + (r0+8)*ROWB + bo + 16);
                aL[mf][0] = *(const unsigned*)(smraw + SM_AL + r0*ROWB + bo);
                aL[mf][1] = *(const unsigned*)(smraw + SM_AL + (r0+8)*ROWB + bo);
                aL[mf][2] = *(const unsigned*)(smraw + SM_AL + r0*ROWB + bo + 16);
                aL[mf][3] = *(const unsigned*)(smraw + SM_AL + (r0+8)*ROWB + bo + 16);
            }
#pragma unroll
            for (int nf = 0; nf < 8; nf++){
                int bi = (ks*16 + NT0 + nf)*64 + lane*2;
                unsigned bh0 = BH[bi], bh1 = BH[bi+1];
                unsigned bl0 = BL[bi], bl1 = BL[bi+1];
#pragma unroll
                for (int mf = 0; mf < 2; mf++){
                    mma16816(cacc[mf][nf], aH[mf], bh0, bh1);
                    mma16816(cacc[mf][nf], aH[mf], bl0, bl1);
                    mma16816(cacc[mf][nf], aL[mf], bh0, bh1);
                }
            }
        }
        __syncthreads();
    }
#pragma unroll
    for (int mf = 0; mf < 2; mf++){
#pragma unroll
        for (int nf = 0; nf < 8; nf++){
            int row0 = nb + M0 + mf*16 + gid;
            int col = NT0*8 + nf*8 + tig*2;
            float2 v0; v0.x = fmaxf(cacc[mf][nf][0], 0.f); v0.y = fmaxf(cacc[mf][nf][1], 0.f);
            float2 v1; v1.x = fmaxf(cacc[mf][nf][2], 0.f); v1.y = fmaxf(cacc[mf][nf][3], 0.f);
            *(float2*)&agg[(size_t)row0*NF + col] = v0;
            *(float2*)&agg[(size_t)(row0+8)*NF + col] = v1;
        }
    }
}

// ---------------- fused pool + edge-compact + readout, both branches ----------------
__global__ void __launch_bounds__(256) pool_fused2(int n, int k, int lev,
        const float* __restrict__ pool_p,
        const int* __restrict__ ei0, const int* __restrict__ ei1){
    __shared__ float s[256];
    __shared__ int pos[256];
    __shared__ unsigned char kf[256];
    __shared__ int maxv[128];
    __shared__ float sumv[128];
    __shared__ int ecnt_s;
    int b = blockIdx.x >> 7, g = blockIdx.x & 127;
    int tid = threadIdx.x;
    int wid = tid >> 5, lane = tid & 31;
    int nodebase = g*n;
    const float* p = pool_p + (b*3 + lev)*NF;
    const float* agg = d_agg[b];
    const int* esrcIn; const int* edstIn; int m; int ebIn;
    if (lev == 0){
        const int* ei = b ? ei1 : ei0;
        esrcIn = ei; edstIn = ei + NE; m = EPG; ebIn = g*EPG;
    } else if (lev == 1){
        esrcIn = d_srcA[b]; edstIn = d_dstA[b]; m = d_ecntA[b*G+g]; ebIn = g*EPG2;
    } else {
        esrcIn = d_srcB[b]; edstIn = d_dstB[b]; m = d_ecntB[b*G+g]; ebIn = g*EPG2;
    }
    for (int i = wid; i < n; i += 8){
        float v = 0.f;
#pragma unroll
        for (int t = 0; t < 4; t++){
            int f = lane + t*32;
            v += agg[(size_t)(nodebase+i)*NF + f] * p[f];
        }
#pragma unroll
        for (int o = 16; o > 0; o >>= 1) v += __shfl_down_sync(0xffffffffu, v, o);
        if (lane == 0) s[i] = 1.0f/(1.0f + expf(-v));
    }
    if (tid < 128){ maxv[tid] = 0; sumv[tid] = 0.f; }
    if (tid == 0) ecnt_s = 0;
    __syncthreads();
    for (int i = tid; i < n; i += 256){
        float si = s[i]; int c = 0;
        for (int j = 0; j < n; j++){
            float sj = s[j];
            c += (sj > si) || (sj == si && j < i);
        }
        kf[i] = (c < k) ? 1 : 0;
    }
    __syncthreads();
    for (int i = tid; i < n; i += 256){
        int c = 0;
        for (int j = 0; j < i; j++) c += kf[j];
        pos[i] = c;
    }
    __syncthreads();
    float* xout = d_xbuf[b];
    for (int t = tid; t < n*NF; t += 256){
        int i = t >> 7, f = t & 127;
        if (kf[i]){
            float v = agg[(size_t)(nodebase+i)*NF + f] * s[i];
            xout[(size_t)(g*k + pos[i])*NF + f] = v;
            atomicMax(&maxv[f], __float_as_int(v));
            atomicAdd(&sumv[f], v);
        }
    }
    if (lev < 2){
        int ebOut = g*EPG2;
        int* esrcOut = (lev == 0) ? d_srcA[b] : d_srcB[b];
        int* edstOut = (lev == 0) ? d_dstA[b] : d_dstB[b];
        for (int e = tid; e < m; e += 256){
            int sN = esrcIn[ebIn+e] - nodebase;
            int dN = edstIn[ebIn+e] - nodebase;
            if (kf[sN] && kf[dN]){
                int slot = atomicAdd(&ecnt_s, 1);
                esrcOut[ebOut+slot] = g*k + pos[sN];
                edstOut[ebOut+slot] = g*k + pos[dN];
            }
        }
    }
    __syncthreads();
    if (tid < 128){
        float* o = &d_read[((size_t)(b*3+lev)*G + g)*256];
        o[tid] = __int_as_float(maxv[tid]);
        o[128 + tid] = sumv[tid] / (float)k;
    }
    if (tid == 0 && lev < 2){
        if (lev == 0) d_ecntA[b*G+g] = ecnt_s; else d_ecntB[b*G+g] = ecnt_s;
    }
}

// ---------------- head: combine readouts + fc_g KAN (256->256), both branches ----------------
__global__ void __launch_bounds__(256) head_fcg(const float* __restrict__ wr,
                                                float* __restrict__ out){
    extern __shared__ float sm[];
    float* X  = sm;                 // [16][256]
    float* Et = sm + 16*256;        // [72][16]
    float* Ws = Et + 72*16;         // [72][128]
    int tid = threadIdx.x;
    int rb = blockIdx.x * 16;
    int ob = blockIdx.y * 128;
    int b  = blockIdx.z;
    float w0 = wr[0], w1 = wr[1], w2 = wr[2];
    for (int idx = tid; idx < 16*256; idx += 256){
        int r = idx >> 8, i = idx & 255;
        int row = rb + r;
        float v;
        if (b == 0){
            float a0 = d_read[((size_t)0*G + row)*256 + i];
            float a1 = d_read[((size_t)1*G + row)*256 + i];
            v = fmaxf(a0, 0.f) + fmaxf(a1, 0.f);
        } else {
            float a0 = d_read[((size_t)3*G + row)*256 + i];
            float a1 = d_read[((size_t)4*G + row)*256 + i];
            float a2 = d_read[((size_t)5*G + row)*256 + i];
            v = w0*fmaxf(a0, 0.f) + w1*fmaxf(a1, 0.f) + w2*fmaxf(a2, 0.f);
        }
        X[idx] = v;
    }
    const float* __restrict__ W = d_wfcgT + (size_t)b*KFC*256;
    int rg = (tid >> 5) * 2;
    int og = (tid & 31) * 4;
    unsigned long long acc[4];
#pragma unroll
    for (int c = 0; c < 4; c++) acc[c] = 0ull;

    for (int c = 0; c < 32; c++){
        int i0 = c*8;
        __syncthreads();
        if (tid < 128){
            int r = tid >> 3, ii = tid & 7;
            float xv = X[r*256 + i0 + ii];
            float bs[8]; bsplines8(xv, bs);
            Et[(ii*9)*16 + r] = xv;
#pragma unroll
            for (int s = 0; s < 8; s++) Et[(ii*9+1+s)*16 + r] = bs[s];
        }
        for (int idx = tid; idx < 72*128; idx += 256){
            int kk = idx >> 7, j = idx & 127;
            Ws[idx] = W[((size_t)c*72 + kk)*256 + ob + j];
        }
        __syncthreads();
#pragma unroll 4
        for (int kk = 0; kk < 72; kk++){
            unsigned long long a = *(const unsigned long long*)&Et[kk*16 + rg];
            float4 w4 = *(const float4*)&Ws[kk*128 + og];
            ffma2(acc[0], a, pk2(w4.x, w4.x));
            ffma2(acc[1], a, pk2(w4.y, w4.y));
            ffma2(acc[2], a, pk2(w4.z, w4.z));
            ffma2(acc[3], a, pk2(w4.w, w4.w));
        }
    }
    int outbase = 128 + b*(G*256);
    float lo[4], hi[4];
#pragma unroll
    for (int c = 0; c < 4; c++) upk2(acc[c], lo[c], hi[c]);
    int row0 = rb + rg, row1 = rb + rg + 1;
    float4 v0; v0.x = lo[0]; v0.y = lo[1]; v0.z = lo[2]; v0.w = lo[3];
    float4 v1; v1.x = hi[0]; v1.y = hi[1]; v1.z = hi[2]; v1.w = hi[3];
    *(float4*)&d_xg[((size_t)b*G + row0)*256 + ob + og] = v0;
    *(float4*)&d_xg[((size_t)b*G + row1)*256 + ob + og] = v1;
    *(float4*)&out[outbase + (size_t)row0*256 + ob + og] = v0;
    *(float4*)&out[outbase + (size_t)row1*256 + ob + og] = v1;
}

// ---------------- head: fc_final KAN (256->1), both branches ----------------
__global__ void __launch_bounds__(256) head_fin(float* __restrict__ out){
    __shared__ float Xs[256];
    __shared__ float red[256];
    int row = blockIdx.x, b = blockIdx.y, tid = threadIdx.x;
    Xs[tid] = d_xg[((size_t)b*G + row)*256 + tid];
    __syncthreads();
    float xv = Xs[tid];
    float bs[8]; bsplines8(xv, bs);
    const float* W = d_wfinT + (size_t)b*KFC + tid*9;
    float acc = xv * W[0];
#pragma unroll
    for (int s = 0; s < 8; s++) acc += bs[s]*W[1+s];
    red[tid] = acc;
    __syncthreads();
    for (int o = 128; o > 0; o >>= 1){
        if (tid < o) red[tid] += red[tid+o];
        __syncthreads();
    }
    if (tid == 0){
        int base = (b == 0) ? 0 : (128 + 2*G*256);
        out[base + row] = red[0];
    }
}

// ---------------- launch ----------------
extern "C" void kernel_launch(void* const* d_in, const int* in_sizes, int n_in,
                              void* d_out, int out_size){
    (void)in_sizes; (void)n_in; (void)out_size;
    const float* x       = (const float*)d_in[0];
    const float* a       = (const float*)d_in[1];
    const float* dt0_w   = (const float*)d_in[2];
    const float* dt0_b   = (const float*)d_in[3];
    const float* dt1_w   = (const float*)d_in[4];
    const float* dt1_b   = (const float*)d_in[5];
    const float* conv_bw = (const float*)d_in[6];
    const float* conv_sw = (const float*)d_in[7];
    const float* fcg_bw  = (const float*)d_in[8];
    const float* fcg_sw  = (const float*)d_in[9];
    const float* fin_bw  = (const float*)d_in[10];
    const float* fin_sw  = (const float*)d_in[11];
    const float* pool_p  = (const float*)d_in[12];
    const float* w_r     = (const float*)d_in[13];
    const int* edge_index = (const int*)d_in[14];
    const int* edge       = (const int*)d_in[15];
    float* out = (float*)d_out;

    cudaFuncSetAttribute(aggregate2,    cudaFuncAttributeMaxDynamicSharedMemorySize, 256*128*4);
    cudaFuncSetAttribute(kan_gemm_mma2, cudaFuncAttributeMaxDynamicSharedMemorySize, SM_TOT);
    cudaFuncSetAttribute(input_linear2, cudaFuncAttributeMaxDynamicSharedMemorySize, (64*96+96*WSP)*4);
    cudaFuncSetAttribute(head_fcg,      cudaFuncAttributeMaxDynamicSharedMemorySize, (16*256+72*16+72*128)*4);

    // launch order keeps kan_gemm_mma2 L0 at slot #4 for the profiler.
    prep_w_mma<<<(6*2*16*5*16*64+255)/256, 256>>>(conv_bw, conv_sw);
    input_linear2<<<dim3(NNODE/64, 2), 256, (64*96+96*WSP)*4>>>(x, a, dt0_w, dt0_b, dt1_w, dt1_b);

    int n = 256;
    for (int lev = 0; lev < 3; lev++){
        int k = n/2;
        int cpb = G*n/TN;
        aggregate2<<<2*G, 256, n*128*4>>>(n, lev, edge_index, edge);
        kan_gemm_mma2<<<2*cpb, 256, SM_TOT>>>(cpb, lev);
        pool_fused2<<<2*G, 256>>>(n, k, lev, pool_p, edge_index, edge);
        n = k;
    }
    prep_fcg<<<(2*KFC*256+255)/256, 256>>>(fcg_bw, fcg_sw);
    prep_fin<<<(2*KFC+255)/256, 256>>>(fin_bw, fin_sw);
    head_fcg<<<dim3(8,2,2), 256, (16*256+72*16+72*128)*4>>>(w_r, out);
    head_fin<<<dim3(G,2), 256>>>(out);
}